// round 1
// baseline (speedup 1.0000x reference)
#include <cuda_runtime.h>
#include <math.h>

// ---------------------------------------------------------------------------
// Fused Equiformer FFN, fp32, packed f32x2 FMA (Blackwell fma.rn.f32x2).
// One CTA = 32 nodes. All intermediates stay in shared memory.
//
// Layout recap (per node):
//   x0 = in[0:128], x1[k][i] = in[128 + k*3 + i] (k<64,i<3),
//   x2[k][i] = in[320 + k*5 + i] (k<32,i<5)
//   h0 = x0 @ W1_0 * inv128 * attr + b1                      (672)
//   scalars = silu(h0[0:384]); g1 = sig(h0[384:576]); g2 = sig(h0[576:672])
//   out[0:128]          = scalars @ W2_0 * inv384 * attr + b2
//   mid1_i = (x1_i @ W1_1 * inv64  * attr) * g1   -> out[128 + o*3 + i] = mid1_i @ W2_1 * inv192 * attr
//   mid2_i = (x2_i @ W1_2 * inv32  * attr) * g2   -> out[320 + o*5 + i] = mid2_i @ W2_2 * inv96  * attr
// ---------------------------------------------------------------------------

#define NODES_PER_CTA 32
#define THREADS 256

// shared memory layout (floats)
#define OFF_X 0                    // 32 * 480
#define OFF_H (32 * 480)           // 32 * 672
#define OFF_M (OFF_H + 32 * 672)   // 32 * 193 (padded mid buffer)
#define OFF_A (OFF_M + 32 * 193)   // 32 (attr)
#define SMEM_FLOATS (OFF_A + 32)

__device__ __forceinline__ unsigned long long pk2(float lo, float hi) {
    unsigned long long r;
    asm("mov.b64 %0, {%1, %2};" : "=l"(r) : "f"(lo), "f"(hi));
    return r;
}
__device__ __forceinline__ void fma2(unsigned long long& acc,
                                     unsigned long long a, unsigned long long b) {
    asm("fma.rn.f32x2 %0, %1, %2, %0;" : "+l"(acc) : "l"(a), "l"(b));
}
__device__ __forceinline__ float2 unpk2(unsigned long long v) {
    float2 f;
    asm("mov.b64 {%0, %1}, %2;" : "=f"(f.x), "=f"(f.y) : "l"(v));
    return f;
}

// Generic small GEMM: out(R x C) = X(R x K) @ W(K x C), W row-major in global.
// Thread tiles are TR rows x 4 cols; cols use packed f32x2 FMA.
// xld(r,k) -> float (shared memory); epi(r,c,val) consumes results.
template <int TR, class XF, class EF>
__device__ __forceinline__ void gemm_stage(int K, int R, int C,
                                           const float* __restrict__ W,
                                           XF xld, EF epi) {
    const int tid = threadIdx.x;
    const int ctiles = C >> 2;
    const int ntiles = (R / TR) * ctiles;
    for (int t = tid; t < ntiles; t += THREADS) {
        const int r0 = (t / ctiles) * TR;
        const int c0 = (t % ctiles) * 4;
        unsigned long long acc[TR][2];
#pragma unroll
        for (int r = 0; r < TR; r++) { acc[r][0] = 0ULL; acc[r][1] = 0ULL; }

        const float4* Wp = reinterpret_cast<const float4*>(W + c0);
#pragma unroll 4
        for (int k = 0; k < K; k++) {
            const float4 w = __ldg(&Wp[k * ctiles]);
            const unsigned long long w01 = pk2(w.x, w.y);
            const unsigned long long w23 = pk2(w.z, w.w);
#pragma unroll
            for (int r = 0; r < TR; r++) {
                const float xv = xld(r0 + r, k);
                const unsigned long long x2 = pk2(xv, xv);
                fma2(acc[r][0], x2, w01);
                fma2(acc[r][1], x2, w23);
            }
        }
#pragma unroll
        for (int r = 0; r < TR; r++) {
            const float2 a = unpk2(acc[r][0]);
            const float2 b = unpk2(acc[r][1]);
            epi(r0 + r, c0 + 0, a.x);
            epi(r0 + r, c0 + 1, a.y);
            epi(r0 + r, c0 + 2, b.x);
            epi(r0 + r, c0 + 3, b.y);
        }
    }
}

__global__ void __launch_bounds__(THREADS)
ffn_fused_kernel(const float* __restrict__ X, const float* __restrict__ attr,
                 const float* __restrict__ W1_0, const float* __restrict__ W1_1,
                 const float* __restrict__ W1_2, const float* __restrict__ b1,
                 const float* __restrict__ W2_0, const float* __restrict__ W2_1,
                 const float* __restrict__ W2_2, const float* __restrict__ b2,
                 float* __restrict__ out, int N) {
    extern __shared__ float sm[];
    float* sX = sm + OFF_X;   // [32][480]
    float* sH = sm + OFF_H;   // [32][672]
    float* sM = sm + OFF_M;   // padded mid buffer
    float* sA = sm + OFF_A;   // [32] attr

    const int tid = threadIdx.x;
    const int nbase = blockIdx.x * NODES_PER_CTA;

    // normalization constants (1/sqrt(fan_in))
    const float inv1_0 = 0.08838834764831843f;   // 1/sqrt(128)
    const float inv1_1 = 0.125f;                 // 1/sqrt(64)
    const float inv1_2 = 0.17677669529663687f;   // 1/sqrt(32)
    const float inv2_0 = 0.05103103630798288f;   // 1/sqrt(384)
    const float inv2_1 = 0.07216878364870323f;   // 1/sqrt(192)
    const float inv2_2 = 0.10206207261596577f;   // 1/sqrt(96)

    // ---- load X tile (coalesced float4) + attr ----
    for (int i = tid; i < NODES_PER_CTA * 120; i += THREADS) {
        const int n = i / 120, c = i % 120;
        const int gn = min(nbase + n, N - 1);
        reinterpret_cast<float4*>(sX)[n * 120 + c] =
            reinterpret_cast<const float4*>(X)[gn * 120 + c];
    }
    if (tid < NODES_PER_CTA) sA[tid] = attr[min(nbase + tid, N - 1)];
    __syncthreads();

    // ---- stage A: h0 = x0 @ W1_0 * inv * attr + b1  (32 x 672, K=128) ----
    gemm_stage<4>(128, 32, 672, W1_0,
        [&](int r, int k) { return sX[r * 480 + k]; },
        [&](int r, int c, float v) {
            sH[r * 672 + c] = v * inv1_0 * sA[r] + __ldg(&b1[c]);
        });
    __syncthreads();

    // ---- activation: silu on [0,384), sigmoid on [384,672) ----
    for (int i = tid; i < NODES_PER_CTA * 672; i += THREADS) {
        const int c = i % 672;
        const float v = sH[i];
        const float s = 1.0f / (1.0f + expf(-v));
        sH[i] = (c < 384) ? v * s : s;
    }
    __syncthreads();

    // ---- stage B: out0 = scalars @ W2_0 * inv * attr + b2  (32 x 128, K=384) ----
    gemm_stage<4>(384, 32, 128, W2_0,
        [&](int r, int k) { return sH[r * 672 + k]; },
        [&](int r, int c, float v) {
            if (nbase + r < N)
                out[(size_t)(nbase + r) * 480 + c] = v * inv2_0 * sA[r] + __ldg(&b2[c]);
        });

    // ---- stage C: l=1 (3 spherical components) ----
    for (int i = 0; i < 3; i++) {
        __syncthreads();
        // mid1_i = (x1_i @ W1_1) * inv * attr * g1   (32 x 192, K=64)
        gemm_stage<2>(64, 32, 192, W1_1,
            [&](int r, int k) { return sX[r * 480 + 128 + k * 3 + i]; },
            [&](int r, int c, float v) {
                sM[r * 193 + c] = v * inv1_1 * sA[r] * sH[r * 672 + 384 + c];
            });
        __syncthreads();
        // out1_i = mid1_i @ W2_1 * inv * attr        (32 x 64, K=192)
        gemm_stage<2>(192, 32, 64, W2_1,
            [&](int r, int k) { return sM[r * 193 + k]; },
            [&](int r, int c, float v) {
                if (nbase + r < N)
                    out[(size_t)(nbase + r) * 480 + 128 + c * 3 + i] = v * inv2_1 * sA[r];
            });
    }

    // ---- stage D: l=2 (5 spherical components) ----
    for (int i = 0; i < 5; i++) {
        __syncthreads();
        // mid2_i = (x2_i @ W1_2) * inv * attr * g2   (32 x 96, K=32)
        gemm_stage<4>(32, 32, 96, W1_2,
            [&](int r, int k) { return sX[r * 480 + 320 + k * 5 + i]; },
            [&](int r, int c, float v) {
                sM[r * 97 + c] = v * inv1_2 * sA[r] * sH[r * 672 + 576 + c];
            });
        __syncthreads();
        // out2_i = mid2_i @ W2_2 * inv * attr        (32 x 32, K=96)
        gemm_stage<1>(96, 32, 32, W2_2,
            [&](int r, int k) { return sM[r * 97 + k]; },
            [&](int r, int c, float v) {
                if (nbase + r < N)
                    out[(size_t)(nbase + r) * 480 + 320 + c * 5 + i] = v * inv2_2 * sA[r];
            });
    }
}

extern "C" void kernel_launch(void* const* d_in, const int* in_sizes, int n_in,
                              void* d_out, int out_size) {
    const float* X    = (const float*)d_in[0];
    const float* attr = (const float*)d_in[1];
    const float* W1_0 = (const float*)d_in[2];
    const float* W1_1 = (const float*)d_in[3];
    const float* W1_2 = (const float*)d_in[4];
    const float* b1   = (const float*)d_in[5];
    const float* W2_0 = (const float*)d_in[6];
    const float* W2_1 = (const float*)d_in[7];
    const float* W2_2 = (const float*)d_in[8];
    const float* b2   = (const float*)d_in[9];
    float* out = (float*)d_out;

    const int N = in_sizes[0] / 480;
    const size_t smem_bytes = (size_t)SMEM_FLOATS * sizeof(float);

    cudaFuncSetAttribute(ffn_fused_kernel,
                         cudaFuncAttributeMaxDynamicSharedMemorySize,
                         (int)smem_bytes);

    const int grid = (N + NODES_PER_CTA - 1) / NODES_PER_CTA;
    ffn_fused_kernel<<<grid, THREADS, smem_bytes>>>(
        X, attr, W1_0, W1_1, W1_2, b1, W2_0, W2_1, W2_2, b2, out, N);
}

// round 4
// speedup vs baseline: 1.8659x; 1.8659x over previous
#include <cuda_runtime.h>
#include <cuda_bf16.h>
#include <cstdint>
#include <math.h>

// ============================================================================
// Equiformer FFN via warp-level mma.sync m16n8k16 bf16 (HMMA), hi/lo 3-term
// split, fp32 accum. Base-ISA only (harness ptxas targets sm_103, no "a").
// CTA = 128 nodes, 8 warps = 4 m-warps x 2 n-warps.
// ============================================================================

#define THREADS 256
#define MAXCTA  782
#define SCRW    1728   // per-node scratch cols: [0,384) scalars, [384,960) mid1,
                       // [960,1440) mid2, [1440,1728) gates

__device__ float g_scr[(size_t)MAXCTA * 128 * SCRW];

// smem byte offsets
#define SM_ATTR 0
#define SM_AH   512
#define SM_AL   (SM_AH + 51200)
#define SM_BH   (SM_AL + 51200)
#define SM_BL   (SM_BH + 34816)
#define SM_TOT  (SM_BL + 34816)   // 172544

__device__ __forceinline__ uint32_t s2u(const void* p) {
    uint32_t a;
    asm("{ .reg .u64 t; cvta.to.shared.u64 t, %1; cvt.u32.u64 %0, t; }" : "=r"(a) : "l"(p));
    return a;
}
__device__ __forceinline__ void ldm_x4(uint32_t d[4], uint32_t a) {
    asm volatile("ldmatrix.sync.aligned.m8n8.x4.shared.b16 {%0,%1,%2,%3}, [%4];"
                 : "=r"(d[0]), "=r"(d[1]), "=r"(d[2]), "=r"(d[3]) : "r"(a));
}
__device__ __forceinline__ void ldm_x2(uint32_t d[2], uint32_t a) {
    asm volatile("ldmatrix.sync.aligned.m8n8.x2.shared.b16 {%0,%1}, [%2];"
                 : "=r"(d[0]), "=r"(d[1]) : "r"(a));
}
__device__ __forceinline__ void mma_bf(float (&c)[4], const uint32_t (&a)[4],
                                       const uint32_t (&b)[2]) {
    asm volatile("mma.sync.aligned.m16n8k16.row.col.f32.bf16.bf16.f32 "
                 "{%0,%1,%2,%3},{%4,%5,%6,%7},{%8,%9},{%0,%1,%2,%3};"
                 : "+f"(c[0]), "+f"(c[1]), "+f"(c[2]), "+f"(c[3])
                 : "r"(a[0]), "r"(a[1]), "r"(a[2]), "r"(a[3]), "r"(b[0]), "r"(b[1]));
}
__device__ __forceinline__ void split(float v, uint16_t& h, uint16_t& l) {
    const __nv_bfloat16 hb = __float2bfloat16_rn(v);
    h = __bfloat16_as_ushort(hb);
    l = __bfloat16_as_ushort(__float2bfloat16_rn(v - __bfloat162float(hb)));
}

template <class F>
__device__ __forceinline__ void fillA(uint16_t* ah, uint16_t* al, int K, int Kpad, F src) {
    for (int idx = threadIdx.x; idx < 128 * K; idx += THREADS) {
        const int r = idx / K, k = idx - r * K;
        uint16_t h, l;
        split(src(r, k), h, l);
        ah[r * Kpad + k] = h;
        al[r * Kpad + k] = l;
    }
}
template <class F>
__device__ __forceinline__ void fillB(uint16_t* bh, uint16_t* bl, int Nc, int K,
                                      int Kpad, F w) {
    for (int idx = threadIdx.x; idx < Nc * K; idx += THREADS) {
        const int k = idx / Nc, n = idx - k * Nc;
        uint16_t h, l;
        split(w(k, n), h, l);
        bh[n * Kpad + k] = h;
        bl[n * Kpad + k] = l;
    }
}

template <int NTW>
__device__ __forceinline__ void zacc(float (&acc)[2][NTW][4]) {
#pragma unroll
    for (int m = 0; m < 2; m++)
#pragma unroll
        for (int j = 0; j < NTW; j++)
#pragma unroll
            for (int q = 0; q < 4; q++) acc[m][j][q] = 0.0f;
}

template <int KT, int NTW>
__device__ __forceinline__ void mma_blk(uint32_t uAH, uint32_t uAL, uint32_t uBH,
                                        uint32_t uBL, int Kpad, int mw, int nw,
                                        int lane, float (&acc)[2][NTW][4]) {
    const int ar  = mw * 32 + (lane & 15);
    const int ak8 = (lane >> 4) * 8;
    const int bn  = lane & 7;
    const int bk8 = ((lane >> 3) & 1) * 8;
#pragma unroll 1
    for (int kt = 0; kt < KT; kt++) {
        const int kb = kt * 16;
        uint32_t Ah[2][4], Al[2][4];
#pragma unroll
        for (int m = 0; m < 2; m++) {
            const uint32_t off = (uint32_t)(((ar + m * 16) * Kpad + kb + ak8) * 2);
            ldm_x4(Ah[m], uAH + off);
            ldm_x4(Al[m], uAL + off);
        }
#pragma unroll
        for (int j = 0; j < NTW; j++) {
            const uint32_t boff =
                (uint32_t)((((nw * NTW + j) * 8 + bn) * Kpad + kb + bk8) * 2);
            uint32_t Bh[2], Bl[2];
            ldm_x2(Bh, uBH + boff);
            ldm_x2(Bl, uBL + boff);
#pragma unroll
            for (int m = 0; m < 2; m++) {
                mma_bf(acc[m][j], Ah[m], Bh);
                mma_bf(acc[m][j], Ah[m], Bl);
                mma_bf(acc[m][j], Al[m], Bh);
            }
        }
    }
}

template <int NTW, class F>
__device__ __forceinline__ void epi_acc(float (&acc)[2][NTW][4], int mw, int nw,
                                        int lane, F f) {
    const int g = lane >> 2, t = lane & 3;
#pragma unroll
    for (int m = 0; m < 2; m++) {
        const int r = mw * 32 + m * 16 + g;
#pragma unroll
        for (int j = 0; j < NTW; j++) {
            const int c = (nw * NTW + j) * 8 + t * 2;
            f(r, c, acc[m][j][0]);
            f(r, c + 1, acc[m][j][1]);
            f(r + 8, c, acc[m][j][2]);
            f(r + 8, c + 1, acc[m][j][3]);
        }
    }
}

__global__ void __launch_bounds__(THREADS, 1)
ffn_hmma(const float* __restrict__ X, const float* __restrict__ attr,
         const float* __restrict__ W1_0, const float* __restrict__ W1_1,
         const float* __restrict__ W1_2, const float* __restrict__ b1,
         const float* __restrict__ W2_0, const float* __restrict__ W2_1,
         const float* __restrict__ W2_2, const float* __restrict__ b2,
         float* __restrict__ out, int Nn, int nct) {
    extern __shared__ char smem[];
    float* sAttr = (float*)(smem + SM_ATTR);
    uint16_t* ah = (uint16_t*)(smem + SM_AH);
    uint16_t* al = (uint16_t*)(smem + SM_AL);
    uint16_t* bh = (uint16_t*)(smem + SM_BH);
    uint16_t* bl = (uint16_t*)(smem + SM_BL);
    const uint32_t uAH = s2u(ah), uAL = s2u(al), uBH = s2u(bh), uBL = s2u(bl);

    const int tid = threadIdx.x, lane = tid & 31, w = tid >> 5;
    const int mw = w & 3, nw = w >> 2;
    float* scr = g_scr + (size_t)blockIdx.x * 128 * SCRW;

    const float I10 = 0.08838834764831843f, I11 = 0.125f, I12 = 0.17677669529663687f;
    const float I20 = 0.05103103630798288f, I21 = 0.07216878364870323f,
                I22 = 0.10206207261596577f;

    for (int b = blockIdx.x; b < nct; b += gridDim.x) {
        const int nbase = b * 128;
        if (tid < 128) sAttr[tid] = attr[min(nbase + tid, Nn - 1)];

        // ===== stage 1: h0 = x0 @ W1_0 (K=128, N=672 in 6x112) =====
        fillA(ah, al, 128, 136, [&](int r, int k) {
            return X[(size_t)min(nbase + r, Nn - 1) * 480 + k];
        });
        for (int ch = 0; ch < 6; ch++) {
            fillB(bh, bl, 112, 128, 136, [&](int k, int n) {
                return W1_0[(size_t)k * 672 + ch * 112 + n];
            });
            __syncthreads();
            float acc[2][7][4];
            zacc(acc);
            mma_blk<8, 7>(uAH, uAL, uBH, uBL, 136, mw, nw, lane, acc);
            __syncthreads();
            epi_acc<7>(acc, mw, nw, lane, [&](int r, int c, float v) {
                const int gc = ch * 112 + c;
                const float val = v * I10 * sAttr[r] + __ldg(&b1[gc]);
                const float sg = 1.0f / (1.0f + __expf(-val));
                if (gc < 384) scr[r * SCRW + gc] = val * sg;
                else          scr[r * SCRW + 1440 + gc - 384] = sg;
            });
            __syncthreads();
        }

        // ===== mid1_i = (x1_i @ W1_1)*g1 (K=64, N=192), i=0..2 =====
        fillB(bh, bl, 192, 64, 72, [&](int k, int n) { return W1_1[(size_t)k * 192 + n]; });
        for (int i = 0; i < 3; i++) {
            fillA(ah, al, 64, 72, [&](int r, int k) {
                return X[(size_t)min(nbase + r, Nn - 1) * 480 + 128 + 3 * k + i];
            });
            __syncthreads();
            float acc[2][12][4];
            zacc(acc);
            mma_blk<4, 12>(uAH, uAL, uBH, uBL, 72, mw, nw, lane, acc);
            __syncthreads();
            epi_acc<12>(acc, mw, nw, lane, [&](int r, int c, float v) {
                scr[r * SCRW + 384 + i * 192 + c] =
                    v * I11 * sAttr[r] * scr[r * SCRW + 1440 + c];
            });
            __syncthreads();
        }

        // ===== mid2_i = (x2_i @ W1_2)*g2 (K=32, N=96), i=0..4 =====
        fillB(bh, bl, 96, 32, 40, [&](int k, int n) { return W1_2[(size_t)k * 96 + n]; });
        for (int i = 0; i < 5; i++) {
            fillA(ah, al, 32, 40, [&](int r, int k) {
                return X[(size_t)min(nbase + r, Nn - 1) * 480 + 320 + 5 * k + i];
            });
            __syncthreads();
            float acc[2][6][4];
            zacc(acc);
            mma_blk<2, 6>(uAH, uAL, uBH, uBL, 40, mw, nw, lane, acc);
            __syncthreads();
            epi_acc<6>(acc, mw, nw, lane, [&](int r, int c, float v) {
                scr[r * SCRW + 960 + i * 96 + c] =
                    v * I12 * sAttr[r] * scr[r * SCRW + 1632 + c];
            });
            __syncthreads();
        }

        // ===== out0 = scalars @ W2_0 (K=384 in 3x128, N=128) =====
        {
            float acc[2][8][4];
            zacc(acc);
            for (int kc = 0; kc < 3; kc++) {
                fillA(ah, al, 128, 136,
                      [&](int r, int k) { return scr[r * SCRW + kc * 128 + k]; });
                fillB(bh, bl, 128, 128, 136, [&](int k, int n) {
                    return W2_0[(size_t)(kc * 128 + k) * 128 + n];
                });
                __syncthreads();
                mma_blk<8, 8>(uAH, uAL, uBH, uBL, 136, mw, nw, lane, acc);
                __syncthreads();
            }
            epi_acc<8>(acc, mw, nw, lane, [&](int r, int c, float v) {
                const int node = nbase + r;
                if (node < Nn)
                    out[(size_t)node * 480 + c] = v * I20 * sAttr[r] + __ldg(&b2[c]);
            });
        }

        // ===== out1_i = mid1_i @ W2_1 (K=192, N=64), i=0..2 =====
        fillB(bh, bl, 64, 192, 200, [&](int k, int n) { return W2_1[(size_t)k * 64 + n]; });
        for (int i = 0; i < 3; i++) {
            fillA(ah, al, 192, 200,
                  [&](int r, int k) { return scr[r * SCRW + 384 + i * 192 + k]; });
            __syncthreads();
            float acc[2][4][4];
            zacc(acc);
            mma_blk<12, 4>(uAH, uAL, uBH, uBL, 200, mw, nw, lane, acc);
            __syncthreads();
            epi_acc<4>(acc, mw, nw, lane, [&](int r, int c, float v) {
                const int node = nbase + r;
                if (node < Nn)
                    out[(size_t)node * 480 + 128 + c * 3 + i] = v * I21 * sAttr[r];
            });
        }

        // ===== out2_i = mid2_i @ W2_2 (K=96, N=32), i=0..4 =====
        fillB(bh, bl, 32, 96, 104, [&](int k, int n) { return W2_2[(size_t)k * 32 + n]; });
        for (int i = 0; i < 5; i++) {
            fillA(ah, al, 96, 104,
                  [&](int r, int k) { return scr[r * SCRW + 960 + i * 96 + k]; });
            __syncthreads();
            float acc[2][2][4];
            zacc(acc);
            mma_blk<6, 2>(uAH, uAL, uBH, uBL, 104, mw, nw, lane, acc);
            __syncthreads();
            epi_acc<2>(acc, mw, nw, lane, [&](int r, int c, float v) {
                const int node = nbase + r;
                if (node < Nn)
                    out[(size_t)node * 480 + 320 + c * 5 + i] = v * I22 * sAttr[r];
            });
        }
        __syncthreads();
    }
}

extern "C" void kernel_launch(void* const* d_in, const int* in_sizes, int n_in,
                              void* d_out, int out_size) {
    const float* X    = (const float*)d_in[0];
    const float* attr = (const float*)d_in[1];
    const float* W1_0 = (const float*)d_in[2];
    const float* W1_1 = (const float*)d_in[3];
    const float* W1_2 = (const float*)d_in[4];
    const float* b1   = (const float*)d_in[5];
    const float* W2_0 = (const float*)d_in[6];
    const float* W2_1 = (const float*)d_in[7];
    const float* W2_2 = (const float*)d_in[8];
    const float* b2   = (const float*)d_in[9];
    float* out = (float*)d_out;

    const int N = in_sizes[0] / 480;
    const int nct = (N + 127) / 128;
    const int grid = nct < MAXCTA ? nct : MAXCTA;

    cudaFuncSetAttribute(ffn_hmma, cudaFuncAttributeMaxDynamicSharedMemorySize, SM_TOT);
    ffn_hmma<<<grid, THREADS, SM_TOT>>>(X, attr, W1_0, W1_1, W1_2, b1,
                                        W2_0, W2_1, W2_2, b2, out, N, nct);
}

// round 5
// speedup vs baseline: 3.0141x; 1.6154x over previous
#include <cuda_runtime.h>
#include <cuda_bf16.h>
#include <cstdint>
#include <math.h>

// ============================================================================
// Equiformer FFN via warp-level mma.sync m16n8k16 bf16 (HMMA), hi/lo 3-term
// split, fp32 accum. 512 threads (4x4 warps), pre-split weights + cp.async.
// ============================================================================

#define THREADS 512
#define MAXCTA  782
#define SCRW    1728   // per-node: [0,384) scalars, [384,960) mid1,
                       // [960,1440) mid2, [1440,1728) gates

__device__ float g_scr[(size_t)MAXCTA * 128 * SCRW];

// pre-split weights, [n][Kpad] bf16 (hi and lo arrays)
#define OFF10 0               // 672 x 136
#define OFF11 91392           // 192 x 72
#define OFF12 105216          // 96 x 40
#define OFF20 109056          // 3 chunks of 128 x 136
#define OFF21 161280          // 64 x 200
#define OFF22 174080          // 32 x 104
#define WTOT  177408
__device__ __nv_bfloat16 g_wh[WTOT];
__device__ __nv_bfloat16 g_wl[WTOT];

// smem byte offsets
#define SM_ATTR 0
#define SM_AH   1024
#define SM_AL   (SM_AH + 51200)           // A: 128 x 200 max
#define SM_BH   (SM_AL + 51200)
#define SM_BL   (SM_BH + 60928)           // B: 224 x 136 max
#define SM_TOT  (SM_BL + 60928)           // 225280

__device__ __forceinline__ uint32_t s2u(const void* p) {
    uint32_t a;
    asm("{ .reg .u64 t; cvta.to.shared.u64 t, %1; cvt.u32.u64 %0, t; }" : "=r"(a) : "l"(p));
    return a;
}
__device__ __forceinline__ void ldm_x4(uint32_t d[4], uint32_t a) {
    asm volatile("ldmatrix.sync.aligned.m8n8.x4.shared.b16 {%0,%1,%2,%3}, [%4];"
                 : "=r"(d[0]), "=r"(d[1]), "=r"(d[2]), "=r"(d[3]) : "r"(a));
}
__device__ __forceinline__ void ldm_x2(uint32_t d[2], uint32_t a) {
    asm volatile("ldmatrix.sync.aligned.m8n8.x2.shared.b16 {%0,%1}, [%2];"
                 : "=r"(d[0]), "=r"(d[1]) : "r"(a));
}
__device__ __forceinline__ void mma_bf(float (&c)[4], const uint32_t (&a)[4],
                                       const uint32_t (&b)[2]) {
    asm volatile("mma.sync.aligned.m16n8k16.row.col.f32.bf16.bf16.f32 "
                 "{%0,%1,%2,%3},{%4,%5,%6,%7},{%8,%9},{%0,%1,%2,%3};"
                 : "+f"(c[0]), "+f"(c[1]), "+f"(c[2]), "+f"(c[3])
                 : "r"(a[0]), "r"(a[1]), "r"(a[2]), "r"(a[3]), "r"(b[0]), "r"(b[1]));
}
__device__ __forceinline__ void split(float v, uint16_t& h, uint16_t& l) {
    const __nv_bfloat16 hb = __float2bfloat16_rn(v);
    h = __bfloat16_as_ushort(hb);
    l = __bfloat16_as_ushort(__float2bfloat16_rn(v - __bfloat162float(hb)));
}
__device__ __forceinline__ void cp16(uint32_t dst, const void* src) {
    asm volatile("cp.async.cg.shared.global [%0], [%1], 16;" :: "r"(dst), "l"(src));
}
#define CP_COMMIT() asm volatile("cp.async.commit_group;" ::: "memory")
#define CP_WAIT()   asm volatile("cp.async.wait_group 0;" ::: "memory")

// B tile copy: linear [n][Kpad] region, pre-split in global -> smem via cp.async
__device__ __forceinline__ void bcopy(uint32_t uBH, uint32_t uBL, int off, int elems) {
    const int chunks = elems >> 3;   // 16B per 8 bf16
    for (int i = threadIdx.x; i < chunks; i += THREADS) {
        cp16(uBH + i * 16, g_wh + off + i * 8);
        cp16(uBL + i * 16, g_wl + off + i * 8);
    }
}

template <class F>
__device__ __forceinline__ void fillA(uint16_t* ah, uint16_t* al, int K, int Kpad, F src) {
    for (int idx = threadIdx.x; idx < 128 * K; idx += THREADS) {
        const int r = idx / K, k = idx - r * K;
        uint16_t h, l;
        split(src(r, k), h, l);
        ah[r * Kpad + k] = h;
        al[r * Kpad + k] = l;
    }
}

template <int NTW>
__device__ __forceinline__ void zacc(float (&acc)[2][NTW][4]) {
#pragma unroll
    for (int m = 0; m < 2; m++)
#pragma unroll
        for (int j = 0; j < NTW; j++)
#pragma unroll
            for (int q = 0; q < 4; q++) acc[m][j][q] = 0.0f;
}

template <int KT, int NTW>
__device__ __forceinline__ void mma_blk(uint32_t uAH, uint32_t uAL, uint32_t uBH,
                                        uint32_t uBL, int Kpad, int mw, int nw,
                                        int lane, float (&acc)[2][NTW][4]) {
    const int ar  = mw * 32 + (lane & 15);
    const int ak8 = (lane >> 4) * 8;
    const int bn  = lane & 7;
    const int bk8 = ((lane >> 3) & 1) * 8;
#pragma unroll 1
    for (int kt = 0; kt < KT; kt++) {
        const int kb = kt * 16;
        uint32_t Ah[2][4], Al[2][4];
#pragma unroll
        for (int m = 0; m < 2; m++) {
            const uint32_t off = (uint32_t)(((ar + m * 16) * Kpad + kb + ak8) * 2);
            ldm_x4(Ah[m], uAH + off);
            ldm_x4(Al[m], uAL + off);
        }
#pragma unroll
        for (int j = 0; j < NTW; j++) {
            const uint32_t boff =
                (uint32_t)((((nw * NTW + j) * 8 + bn) * Kpad + kb + bk8) * 2);
            uint32_t Bh[2], Bl[2];
            ldm_x2(Bh, uBH + boff);
            ldm_x2(Bl, uBL + boff);
#pragma unroll
            for (int m = 0; m < 2; m++) {
                mma_bf(acc[m][j], Ah[m], Bh);
                mma_bf(acc[m][j], Ah[m], Bl);
                mma_bf(acc[m][j], Al[m], Bh);
            }
        }
    }
}

template <int NTW, class F>
__device__ __forceinline__ void epi_acc(float (&acc)[2][NTW][4], int mw, int nw,
                                        int lane, F f) {
    const int g = lane >> 2, t = lane & 3;
#pragma unroll
    for (int m = 0; m < 2; m++) {
        const int r = mw * 32 + m * 16 + g;
#pragma unroll
        for (int j = 0; j < NTW; j++) {
            const int c = (nw * NTW + j) * 8 + t * 2;
            f(r, c, acc[m][j][0]);
            f(r, c + 1, acc[m][j][1]);
            f(r + 8, c, acc[m][j][2]);
            f(r + 8, c + 1, acc[m][j][3]);
        }
    }
}

// ---- weight prep: fp32 [K][N] -> hi/lo bf16 [n][Kpad] ----
__device__ __forceinline__ void prep_mat(const float* __restrict__ W, int K, int N,
                                         int Kpad, int base) {
    const int tot = K * N;
    for (int idx = blockIdx.x * blockDim.x + threadIdx.x; idx < tot;
         idx += gridDim.x * blockDim.x) {
        const int k = idx / N, n = idx - k * N;
        uint16_t h, l;
        split(__ldg(&W[idx]), h, l);
        g_wh[base + n * Kpad + k] = __ushort_as_bfloat16(h);
        g_wl[base + n * Kpad + k] = __ushort_as_bfloat16(l);
    }
}

__global__ void prep_kernel(const float* W1_0, const float* W1_1, const float* W1_2,
                            const float* W2_0, const float* W2_1, const float* W2_2) {
    prep_mat(W1_0, 128, 672, 136, OFF10);
    prep_mat(W1_1, 64, 192, 72, OFF11);
    prep_mat(W1_2, 32, 96, 40, OFF12);
    // W2_0: 3 K-chunks, each stored as its own [128 n][136] tile
    for (int kc = 0; kc < 3; kc++) {
        const int tot = 128 * 128;
        for (int idx = blockIdx.x * blockDim.x + threadIdx.x; idx < tot;
             idx += gridDim.x * blockDim.x) {
            const int k = idx / 128, n = idx - k * 128;
            uint16_t h, l;
            split(__ldg(&W2_0[(size_t)(kc * 128 + k) * 128 + n]), h, l);
            const int o = OFF20 + kc * 128 * 136 + n * 136 + k;
            g_wh[o] = __ushort_as_bfloat16(h);
            g_wl[o] = __ushort_as_bfloat16(l);
        }
    }
    prep_mat(W2_1, 192, 64, 200, OFF21);
    prep_mat(W2_2, 96, 32, 104, OFF22);
}

__global__ void __launch_bounds__(THREADS, 1)
ffn_hmma(const float* __restrict__ X, const float* __restrict__ attr,
         const float* __restrict__ b1, const float* __restrict__ b2,
         float* __restrict__ out, int Nn) {
    extern __shared__ char smem[];
    float* sAttr = (float*)(smem + SM_ATTR);
    uint16_t* ah = (uint16_t*)(smem + SM_AH);
    uint16_t* al = (uint16_t*)(smem + SM_AL);
    const uint32_t uAH = s2u(ah), uAL = s2u(al);
    const uint32_t uBH = s2u(smem + SM_BH), uBL = s2u(smem + SM_BL);

    const int tid = threadIdx.x, lane = tid & 31, w = tid >> 5;
    const int mw = w & 3, nw = w >> 2;
    const int nbase = blockIdx.x * 128;
    float* scr = g_scr + (size_t)blockIdx.x * 128 * SCRW;

    const float I10 = 0.08838834764831843f, I11 = 0.125f, I12 = 0.17677669529663687f;
    const float I20 = 0.05103103630798288f, I21 = 0.07216878364870323f,
                I22 = 0.10206207261596577f;

    if (tid < 128) sAttr[tid] = attr[min(nbase + tid, Nn - 1)];

    // ===== stage 1: h0 = x0 @ W1_0 (K=128, N=672 in 3x224) =====
    bcopy(uBH, uBL, OFF10, 224 * 136);
    CP_COMMIT();
    fillA(ah, al, 128, 136, [&](int r, int k) {
        return X[(size_t)min(nbase + r, Nn - 1) * 480 + k];
    });
    for (int ch = 0; ch < 3; ch++) {
        CP_WAIT();
        __syncthreads();
        float acc[2][7][4];
        zacc(acc);
        mma_blk<8, 7>(uAH, uAL, uBH, uBL, 136, mw, nw, lane, acc);
        __syncthreads();
        if (ch < 2) {
            bcopy(uBH, uBL, OFF10 + (ch + 1) * 224 * 136, 224 * 136);
            CP_COMMIT();
        }
        epi_acc<7>(acc, mw, nw, lane, [&](int r, int c, float v) {
            const int gc = ch * 224 + c;
            const float val = v * I10 * sAttr[r] + __ldg(&b1[gc]);
            const float sg = 1.0f / (1.0f + __expf(-val));
            if (gc < 384) scr[r * SCRW + gc] = val * sg;
            else          scr[r * SCRW + 1440 + gc - 384] = sg;
        });
    }

    // ===== mid1_i = (x1_i @ W1_1)*g1 (K=64, N=192), i=0..2 =====
    __syncthreads();
    bcopy(uBH, uBL, OFF11, 192 * 72);
    CP_COMMIT();
    for (int i = 0; i < 3; i++) {
        fillA(ah, al, 64, 72, [&](int r, int k) {
            return X[(size_t)min(nbase + r, Nn - 1) * 480 + 128 + 3 * k + i];
        });
        CP_WAIT();
        __syncthreads();
        float acc[2][6][4];
        zacc(acc);
        mma_blk<4, 6>(uAH, uAL, uBH, uBL, 72, mw, nw, lane, acc);
        __syncthreads();
        epi_acc<6>(acc, mw, nw, lane, [&](int r, int c, float v) {
            scr[r * SCRW + 384 + i * 192 + c] =
                v * I11 * sAttr[r] * scr[r * SCRW + 1440 + c];
        });
    }

    // ===== mid2_i = (x2_i @ W1_2)*g2 (K=32, N=96), i=0..4 =====
    __syncthreads();
    bcopy(uBH, uBL, OFF12, 96 * 40);
    CP_COMMIT();
    for (int i = 0; i < 5; i++) {
        fillA(ah, al, 32, 40, [&](int r, int k) {
            return X[(size_t)min(nbase + r, Nn - 1) * 480 + 320 + 5 * k + i];
        });
        CP_WAIT();
        __syncthreads();
        float acc[2][3][4];
        zacc(acc);
        mma_blk<2, 3>(uAH, uAL, uBH, uBL, 40, mw, nw, lane, acc);
        __syncthreads();
        epi_acc<3>(acc, mw, nw, lane, [&](int r, int c, float v) {
            scr[r * SCRW + 960 + i * 96 + c] =
                v * I12 * sAttr[r] * scr[r * SCRW + 1632 + c];
        });
    }

    // ===== out0 = scalars @ W2_0 (K=384 in 3x128, N=128) =====
    {
        float acc[2][4][4];
        zacc(acc);
        for (int kc = 0; kc < 3; kc++) {
            __syncthreads();
            bcopy(uBH, uBL, OFF20 + kc * 128 * 136, 128 * 136);
            CP_COMMIT();
            fillA(ah, al, 128, 136,
                  [&](int r, int k) { return scr[r * SCRW + kc * 128 + k]; });
            CP_WAIT();
            __syncthreads();
            mma_blk<8, 4>(uAH, uAL, uBH, uBL, 136, mw, nw, lane, acc);
        }
        __syncthreads();
        epi_acc<4>(acc, mw, nw, lane, [&](int r, int c, float v) {
            const int node = nbase + r;
            if (node < Nn)
                out[(size_t)node * 480 + c] = v * I20 * sAttr[r] + __ldg(&b2[c]);
        });
    }

    // ===== out1_i = mid1_i @ W2_1 (K=192, N=64), i=0..2 =====
    bcopy(uBH, uBL, OFF21, 64 * 200);
    CP_COMMIT();
    for (int i = 0; i < 3; i++) {
        fillA(ah, al, 192, 200,
              [&](int r, int k) { return scr[r * SCRW + 384 + i * 192 + k]; });
        CP_WAIT();
        __syncthreads();
        float acc[2][2][4];
        zacc(acc);
        mma_blk<12, 2>(uAH, uAL, uBH, uBL, 200, mw, nw, lane, acc);
        __syncthreads();
        epi_acc<2>(acc, mw, nw, lane, [&](int r, int c, float v) {
            const int node = nbase + r;
            if (node < Nn)
                out[(size_t)node * 480 + 128 + c * 3 + i] = v * I21 * sAttr[r];
        });
    }

    // ===== out2_i = mid2_i @ W2_2 (K=96, N=32), i=0..4 =====
    bcopy(uBH, uBL, OFF22, 32 * 104);
    CP_COMMIT();
    for (int i = 0; i < 5; i++) {
        fillA(ah, al, 96, 104,
              [&](int r, int k) { return scr[r * SCRW + 960 + i * 96 + k]; });
        CP_WAIT();
        __syncthreads();
        float acc[2][1][4];
        zacc(acc);
        mma_blk<6, 1>(uAH, uAL, uBH, uBL, 104, mw, nw, lane, acc);
        __syncthreads();
        epi_acc<1>(acc, mw, nw, lane, [&](int r, int c, float v) {
            const int node = nbase + r;
            if (node < Nn)
                out[(size_t)node * 480 + 320 + c * 5 + i] = v * I22 * sAttr[r];
        });
    }
}

extern "C" void kernel_launch(void* const* d_in, const int* in_sizes, int n_in,
                              void* d_out, int out_size) {
    const float* X    = (const float*)d_in[0];
    const float* attr = (const float*)d_in[1];
    const float* W1_0 = (const float*)d_in[2];
    const float* W1_1 = (const float*)d_in[3];
    const float* W1_2 = (const float*)d_in[4];
    const float* b1   = (const float*)d_in[5];
    const float* W2_0 = (const float*)d_in[6];
    const float* W2_1 = (const float*)d_in[7];
    const float* W2_2 = (const float*)d_in[8];
    const float* b2   = (const float*)d_in[9];
    float* out = (float*)d_out;

    const int N = in_sizes[0] / 480;
    const int nct = (N + 127) / 128;

    prep_kernel<<<160, 256>>>(W1_0, W1_1, W1_2, W2_0, W2_1, W2_2);
    cudaFuncSetAttribute(ffn_hmma, cudaFuncAttributeMaxDynamicSharedMemorySize, SM_TOT);
    ffn_hmma<<<nct, THREADS, SM_TOT>>>(X, attr, b1, b2, out, N);
}

// round 6
// speedup vs baseline: 4.3243x; 1.4347x over previous
#include <cuda_runtime.h>
#include <cuda_bf16.h>
#include <cstdint>
#include <math.h>

// ============================================================================
// Equiformer FFN, warp-level mma.sync m16n8k16 bf16 hi/lo 3-term split.
// 512 threads (16 warps). Components batched by M-stacking; stage-2 operands
// kept as hi/lo bf16 in global scratch and staged with cp.async only.
// ============================================================================

#define THREADS 512
#define NW      16
#define MAXCTA  782

// ---- pre-split weights [n][Kpad] bf16 ----
#define OFF10 0               // 672 x 136
#define OFF11 91392           // 192 x 72
#define OFF12 105216          // 96 x 40
#define OFF20 109056          // 3 x (128 x 136)
#define OFF21 161280          // 64 x 200
#define OFF22 174080          // 32 x 104
#define WTOT  177408
__device__ __align__(16) uint16_t g_wh[WTOT];
__device__ __align__(16) uint16_t g_wl[WTOT];

// ---- per-CTA scratch (hi/lo bf16 in smem-matching layout + fp32 gates) ----
#define SC_STR 50176   // 128 x 392
#define M1_STR 76800   // 384 x 200
#define M2_STR 66560   // 640 x 104
#define GT_STR 36864   // 128 x 288
__device__ __align__(16) uint16_t g_sc_hi[(size_t)MAXCTA * SC_STR];
__device__ __align__(16) uint16_t g_sc_lo[(size_t)MAXCTA * SC_STR];
__device__ __align__(16) uint16_t g_m1_hi[(size_t)MAXCTA * M1_STR];
__device__ __align__(16) uint16_t g_m1_lo[(size_t)MAXCTA * M1_STR];
__device__ __align__(16) uint16_t g_m2_hi[(size_t)MAXCTA * M2_STR];
__device__ __align__(16) uint16_t g_m2_lo[(size_t)MAXCTA * M2_STR];
__device__ __align__(16) float    g_gate[(size_t)MAXCTA * GT_STR];

#define SM_TOT 205824

__device__ __forceinline__ uint32_t s2u(const void* p) {
    uint32_t a;
    asm("{ .reg .u64 t; cvta.to.shared.u64 t, %1; cvt.u32.u64 %0, t; }" : "=r"(a) : "l"(p));
    return a;
}
__device__ __forceinline__ void ldm_x4(uint32_t d[4], uint32_t a) {
    asm volatile("ldmatrix.sync.aligned.m8n8.x4.shared.b16 {%0,%1,%2,%3}, [%4];"
                 : "=r"(d[0]), "=r"(d[1]), "=r"(d[2]), "=r"(d[3]) : "r"(a));
}
__device__ __forceinline__ void ldm_x2(uint32_t d[2], uint32_t a) {
    asm volatile("ldmatrix.sync.aligned.m8n8.x2.shared.b16 {%0,%1}, [%2];"
                 : "=r"(d[0]), "=r"(d[1]) : "r"(a));
}
__device__ __forceinline__ void mma_bf(float (&c)[4], const uint32_t (&a)[4],
                                       const uint32_t (&b)[2]) {
    asm volatile("mma.sync.aligned.m16n8k16.row.col.f32.bf16.bf16.f32 "
                 "{%0,%1,%2,%3},{%4,%5,%6,%7},{%8,%9},{%0,%1,%2,%3};"
                 : "+f"(c[0]), "+f"(c[1]), "+f"(c[2]), "+f"(c[3])
                 : "r"(a[0]), "r"(a[1]), "r"(a[2]), "r"(a[3]), "r"(b[0]), "r"(b[1]));
}
__device__ __forceinline__ void split(float v, uint16_t& h, uint16_t& l) {
    const __nv_bfloat16 hb = __float2bfloat16_rn(v);
    h = __bfloat16_as_ushort(hb);
    l = __bfloat16_as_ushort(__float2bfloat16_rn(v - __bfloat162float(hb)));
}
// pack two values' hi/lo into uint32 pairs and store to scratch
__device__ __forceinline__ void st_pair(uint16_t* baseH, uint16_t* baseL, int idx,
                                        float v0, float v1) {
    uint16_t h0, l0, h1, l1;
    split(v0, h0, l0);
    split(v1, h1, l1);
    *reinterpret_cast<uint32_t*>(baseH + idx) = (uint32_t)h0 | ((uint32_t)h1 << 16);
    *reinterpret_cast<uint32_t*>(baseL + idx) = (uint32_t)l0 | ((uint32_t)l1 << 16);
}
__device__ __forceinline__ void cp16(uint32_t dst, const void* src) {
    asm volatile("cp.async.cg.shared.global [%0], [%1], 16;" :: "r"(dst), "l"(src));
}
#define CP_COMMIT() asm volatile("cp.async.commit_group;" ::: "memory")
#define CP_WAIT()   asm volatile("cp.async.wait_group 0;" ::: "memory")

__device__ __forceinline__ void cpy_lin(uint32_t dH, uint32_t dL,
                                        const uint16_t* sH, const uint16_t* sL, int elems) {
    const int chunks = elems >> 3;
    for (int i = threadIdx.x; i < chunks; i += THREADS) {
        cp16(dH + i * 16, sH + i * 8);
        cp16(dL + i * 16, sL + i * 8);
    }
}
// per-row copy: rows x (c16 chunks of 16B), src row stride in elements
__device__ __forceinline__ void cpy_rows(uint32_t dH, uint32_t dL,
                                         const uint16_t* sH, const uint16_t* sL,
                                         int rows, int c16, int sStr, int sOff, int dRowB) {
    const int tot = rows * c16;
    for (int i = threadIdx.x; i < tot; i += THREADS) {
        const int r = i / c16, ch = i - r * c16;
        const uint32_t d = r * dRowB + ch * 16;
        const int s = r * sStr + sOff + ch * 8;
        cp16(dH + d, sH + s);
        cp16(dL + d, sL + s);
    }
}

template <int NTW>
__device__ __forceinline__ void zacc(float (&acc)[2][NTW][4]) {
#pragma unroll
    for (int m = 0; m < 2; m++)
#pragma unroll
        for (int j = 0; j < NTW; j++)
#pragma unroll
            for (int q = 0; q < 4; q++) acc[m][j][q] = 0.0f;
}

template <int KT, int NTW>
__device__ __forceinline__ void mma_tile(uint32_t uAH, uint32_t uAL, uint32_t uBH,
                                         uint32_t uBL, int Kpad, int rowBase, int n8Base,
                                         int lane, float (&acc)[2][NTW][4]) {
    const int ar  = rowBase + (lane & 15);
    const int ak8 = (lane >> 4) * 8;
    const int bn  = lane & 7;
    const int bk8 = ((lane >> 3) & 1) * 8;
#pragma unroll 1
    for (int kt = 0; kt < KT; kt++) {
        const int kb = kt * 16;
        uint32_t Ah[2][4], Al[2][4];
#pragma unroll
        for (int m = 0; m < 2; m++) {
            const uint32_t off = (uint32_t)(((ar + m * 16) * Kpad + kb + ak8) * 2);
            ldm_x4(Ah[m], uAH + off);
            ldm_x4(Al[m], uAL + off);
        }
#pragma unroll
        for (int j = 0; j < NTW; j++) {
            const uint32_t boff =
                (uint32_t)((((n8Base + j) * 8 + bn) * Kpad + kb + bk8) * 2);
            uint32_t Bh[2], Bl[2];
            ldm_x2(Bh, uBH + boff);
            ldm_x2(Bl, uBL + boff);
#pragma unroll
            for (int m = 0; m < 2; m++) {
                mma_bf(acc[m][j], Ah[m], Bh);
                mma_bf(acc[m][j], Ah[m], Bl);
                mma_bf(acc[m][j], Al[m], Bh);
            }
        }
    }
}

// run all warp tiles of a phase; f(r, c, v0, v1) consumes column pairs
template <int KT, int NTW, class EF>
__device__ __forceinline__ void run_phase(uint32_t uAH, uint32_t uAL, uint32_t uBH,
                                          uint32_t uBL, int Kpad, int Mt, int Nt,
                                          int w, int lane, EF f) {
    const int g = lane >> 2, t2 = lane & 3;
    for (int t = w; t < Mt * Nt; t += NW) {
        const int mt = t / Nt, nt = t - mt * Nt;
        float acc[2][NTW][4];
        zacc<NTW>(acc);
        mma_tile<KT, NTW>(uAH, uAL, uBH, uBL, Kpad, mt * 32, nt * NTW, lane, acc);
#pragma unroll
        for (int m = 0; m < 2; m++) {
            const int r = mt * 32 + m * 16 + g;
#pragma unroll
            for (int j = 0; j < NTW; j++) {
                const int c = (nt * NTW + j) * 8 + t2 * 2;
                f(r, c, acc[m][j][0], acc[m][j][1]);
                f(r + 8, c, acc[m][j][2], acc[m][j][3]);
            }
        }
    }
}

// ---- weight prep ----
__device__ __forceinline__ void prep_mat(const float* __restrict__ W, int K, int N,
                                         int Kpad, int base) {
    const int tot = K * N;
    for (int idx = blockIdx.x * blockDim.x + threadIdx.x; idx < tot;
         idx += gridDim.x * blockDim.x) {
        const int k = idx / N, n = idx - k * N;
        uint16_t h, l;
        split(__ldg(&W[idx]), h, l);
        g_wh[base + n * Kpad + k] = h;
        g_wl[base + n * Kpad + k] = l;
    }
}
__global__ void prep_kernel(const float* W1_0, const float* W1_1, const float* W1_2,
                            const float* W2_0, const float* W2_1, const float* W2_2) {
    prep_mat(W1_0, 128, 672, 136, OFF10);
    prep_mat(W1_1, 64, 192, 72, OFF11);
    prep_mat(W1_2, 32, 96, 40, OFF12);
    for (int kc = 0; kc < 3; kc++) {
        for (int idx = blockIdx.x * blockDim.x + threadIdx.x; idx < 128 * 128;
             idx += gridDim.x * blockDim.x) {
            const int k = idx / 128, n = idx - k * 128;
            uint16_t h, l;
            split(__ldg(&W2_0[(size_t)(kc * 128 + k) * 128 + n]), h, l);
            g_wh[OFF20 + kc * 128 * 136 + n * 136 + k] = h;
            g_wl[OFF20 + kc * 128 * 136 + n * 136 + k] = l;
        }
    }
    prep_mat(W2_1, 192, 64, 200, OFF21);
    prep_mat(W2_2, 96, 32, 104, OFF22);
}

__global__ void __launch_bounds__(THREADS, 1)
ffn_hmma(const float* __restrict__ X, const float* __restrict__ attr,
         const float* __restrict__ b1, const float* __restrict__ b2,
         float* __restrict__ out, int Nn) {
    extern __shared__ char smem[];
    float* sAttr = (float*)smem;
    const uint32_t sb = s2u(smem);
    uint16_t* sm16 = (uint16_t*)(smem + 1024);

    const int tid = threadIdx.x, lane = tid & 31, w = tid >> 5;
    const int nbase = blockIdx.x * 128;
    const size_t cta = blockIdx.x;
    uint16_t* scH = g_sc_hi + cta * SC_STR;
    uint16_t* scL = g_sc_lo + cta * SC_STR;
    uint16_t* m1H = g_m1_hi + cta * M1_STR;
    uint16_t* m1L = g_m1_lo + cta * M1_STR;
    uint16_t* m2H = g_m2_hi + cta * M2_STR;
    uint16_t* m2L = g_m2_lo + cta * M2_STR;
    float* gate = g_gate + cta * GT_STR;

    const float I10 = 0.08838834764831843f, I11 = 0.125f, I12 = 0.17677669529663687f;
    const float I20 = 0.05103103630798288f, I21 = 0.07216878364870323f,
                I22 = 0.10206207261596577f;

    if (tid < 128) sAttr[tid] = attr[min(nbase + tid, Nn - 1)];

    // ===== h0 = x0 @ W1_0 (128 x 672 x 128), 3 N-chunks of 224 =====
    {
        const uint32_t uAH = sb + 1024, uAL = sb + 35840;
        const uint32_t uBH = sb + 70656, uBL = sb + 131584;
        uint16_t* ah = sm16;            // 128 x 136
        uint16_t* al = sm16 + 17408;
        // A fill (conversion) once
        for (int idx = tid; idx < 128 * 128; idx += THREADS) {
            const int r = idx >> 7, k = idx & 127;
            uint16_t h, l;
            split(__ldg(&X[(size_t)min(nbase + r, Nn - 1) * 480 + k]), h, l);
            ah[r * 136 + k] = h;
            al[r * 136 + k] = l;
        }
        for (int ch = 0; ch < 3; ch++) {
            cpy_lin(uBH, uBL, g_wh + OFF10 + ch * 224 * 136,
                    g_wl + OFF10 + ch * 224 * 136, 224 * 136);
            CP_COMMIT();
            CP_WAIT();
            __syncthreads();
            run_phase<8, 7>(uAH, uAL, uBH, uBL, 136, 4, 4, w, lane,
                [&](int r, int c, float v0, float v1) {
                    const int gc = ch * 224 + c;
                    const float a = sAttr[r] * I10;
                    float x0 = v0 * a + __ldg(&b1[gc]);
                    float x1 = v1 * a + __ldg(&b1[gc + 1]);
                    const float s0 = 1.0f / (1.0f + __expf(-x0));
                    const float s1 = 1.0f / (1.0f + __expf(-x1));
                    if (gc < 384) {
                        st_pair(scH, scL, r * 392 + gc, x0 * s0, x1 * s1);
                    } else {
                        *reinterpret_cast<float2*>(gate + r * 288 + gc - 384) =
                            make_float2(s0, s1);
                    }
                });
            __syncthreads();
        }
    }

    // ===== mid1 = stacked(x1_i) @ W1_1 (384 x 192 x 64), gated =====
    {
        const uint32_t uAH = sb + 1024, uAL = sb + 56320;
        const uint32_t uBH = sb + 111616, uBL = sb + 139264;
        uint16_t* ah = sm16;            // 384 x 72
        uint16_t* al = sm16 + 27648;
        cpy_lin(uBH, uBL, g_wh + OFF11, g_wl + OFF11, 192 * 72);
        CP_COMMIT();
        for (int idx = tid; idx < 384 * 64; idx += THREADS) {
            const int row = idx >> 6, k = idx & 63;
            const int i = row >> 7, r = row & 127;
            uint16_t h, l;
            split(__ldg(&X[(size_t)min(nbase + r, Nn - 1) * 480 + 128 + 3 * k + i]), h, l);
            ah[row * 72 + k] = h;
            al[row * 72 + k] = l;
        }
        CP_WAIT();
        __syncthreads();
        run_phase<4, 4>(uAH, uAL, uBH, uBL, 72, 12, 6, w, lane,
            [&](int row, int c, float v0, float v1) {
                const int r = row & 127;
                const float a = sAttr[r] * I11;
                const float2 gg = *reinterpret_cast<const float2*>(gate + r * 288 + c);
                st_pair(m1H, m1L, row * 200 + c, v0 * a * gg.x, v1 * a * gg.y);
            });
        __syncthreads();
    }

    // ===== mid2 = stacked(x2_i) @ W1_2 (640 x 96 x 32), gated =====
    {
        const uint32_t uAH = sb + 1024, uAL = sb + 52224;
        const uint32_t uBH = sb + 103424, uBL = sb + 111104;
        uint16_t* ah = sm16;            // 640 x 40
        uint16_t* al = sm16 + 25600;
        cpy_lin(uBH, uBL, g_wh + OFF12, g_wl + OFF12, 96 * 40);
        CP_COMMIT();
        for (int idx = tid; idx < 640 * 32; idx += THREADS) {
            const int row = idx >> 5, k = idx & 31;
            const int i = row >> 7, r = row & 127;
            uint16_t h, l;
            split(__ldg(&X[(size_t)min(nbase + r, Nn - 1) * 480 + 320 + 5 * k + i]), h, l);
            ah[row * 40 + k] = h;
            al[row * 40 + k] = l;
        }
        CP_WAIT();
        __syncthreads();
        run_phase<2, 4>(uAH, uAL, uBH, uBL, 40, 20, 3, w, lane,
            [&](int row, int c, float v0, float v1) {
                const int r = row & 127;
                const float a = sAttr[r] * I12;
                const float2 gg =
                    *reinterpret_cast<const float2*>(gate + r * 288 + 192 + c);
                st_pair(m2H, m2L, row * 104 + c, v0 * a * gg.x, v1 * a * gg.y);
            });
        __syncthreads();
    }

    // ===== out0 = scalars @ W2_0 (128 x 128 x 384), 3 K-chunks =====
    {
        const uint32_t uAH = sb + 1024, uAL = sb + 35840;
        const uint32_t uBH = sb + 70656, uBL = sb + 105472;
        float acc[2][4][4];
        zacc<4>(acc);
        for (int kc = 0; kc < 3; kc++) {
            cpy_rows(uAH, uAL, scH, scL, 128, 16, 392, kc * 128, 272);
            cpy_lin(uBH, uBL, g_wh + OFF20 + kc * 128 * 136,
                    g_wl + OFF20 + kc * 128 * 136, 128 * 136);
            CP_COMMIT();
            CP_WAIT();
            __syncthreads();
            mma_tile<8, 4>(uAH, uAL, uBH, uBL, 136, (w >> 2) * 32, (w & 3) * 4, lane, acc);
            __syncthreads();
        }
        const int g = lane >> 2, t2 = lane & 3;
#pragma unroll
        for (int m = 0; m < 2; m++) {
            const int r = (w >> 2) * 32 + m * 16 + g;
            const int node = nbase + r;
            const float a = sAttr[r] * I20;
#pragma unroll
            for (int j = 0; j < 4; j++) {
                const int c = ((w & 3) * 4 + j) * 8 + t2 * 2;
                if (node < Nn) {
                    float2 v = make_float2(acc[m][j][0] * a + __ldg(&b2[c]),
                                           acc[m][j][1] * a + __ldg(&b2[c + 1]));
                    *reinterpret_cast<float2*>(out + (size_t)node * 480 + c) = v;
                }
                const int node2 = node + 8;
                if (node2 < Nn) {
                    float2 v = make_float2(acc[m][j][2] * a + __ldg(&b2[c]),
                                           acc[m][j][3] * a + __ldg(&b2[c + 1]));
                    *reinterpret_cast<float2*>(out + (size_t)node2 * 480 + c) = v;
                }
            }
        }
    }

    // ===== out1 = mid1 @ W2_1 (384 x 64 x 192), 2 M-chunks of 192 =====
    {
        const uint32_t uAH = sb + 1024, uAL = sb + 77824;
        const uint32_t uBH = sb + 154624, uBL = sb + 180224;
        for (int mc = 0; mc < 2; mc++) {
            __syncthreads();
            cpy_lin(uAH, uAL, m1H + mc * 192 * 200, m1L + mc * 192 * 200, 192 * 200);
            if (mc == 0) cpy_lin(uBH, uBL, g_wh + OFF21, g_wl + OFF21, 64 * 200);
            CP_COMMIT();
            CP_WAIT();
            __syncthreads();
            run_phase<12, 2>(uAH, uAL, uBH, uBL, 200, 6, 4, w, lane,
                [&](int row, int c, float v0, float v1) {
                    const int grow = mc * 192 + row;
                    const int i = grow >> 7, r = grow & 127;
                    const int node = nbase + r;
                    if (node < Nn) {
                        const float a = sAttr[r] * I21;
                        out[(size_t)node * 480 + 128 + c * 3 + i] = v0 * a;
                        out[(size_t)node * 480 + 128 + (c + 1) * 3 + i] = v1 * a;
                    }
                });
        }
    }

    // ===== out2 = mid2 @ W2_2 (640 x 32 x 96), 2 M-chunks of 320 =====
    {
        const uint32_t uAH = sb + 1024, uAL = sb + 67584;
        const uint32_t uBH = sb + 134144, uBL = sb + 140800;
        for (int mc = 0; mc < 2; mc++) {
            __syncthreads();
            cpy_lin(uAH, uAL, m2H + mc * 320 * 104, m2L + mc * 320 * 104, 320 * 104);
            if (mc == 0) cpy_lin(uBH, uBL, g_wh + OFF22, g_wl + OFF22, 32 * 104);
            CP_COMMIT();
            CP_WAIT();
            __syncthreads();
            run_phase<6, 2>(uAH, uAL, uBH, uBL, 104, 10, 2, w, lane,
                [&](int row, int c, float v0, float v1) {
                    const int grow = mc * 320 + row;
                    const int i = grow >> 7, r = grow & 127;
                    const int node = nbase + r;
                    if (node < Nn) {
                        const float a = sAttr[r] * I22;
                        out[(size_t)node * 480 + 320 + c * 5 + i] = v0 * a;
                        out[(size_t)node * 480 + 320 + (c + 1) * 5 + i] = v1 * a;
                    }
                });
        }
    }
}

extern "C" void kernel_launch(void* const* d_in, const int* in_sizes, int n_in,
                              void* d_out, int out_size) {
    const float* X    = (const float*)d_in[0];
    const float* attr = (const float*)d_in[1];
    const float* W1_0 = (const float*)d_in[2];
    const float* W1_1 = (const float*)d_in[3];
    const float* W1_2 = (const float*)d_in[4];
    const float* b1   = (const float*)d_in[5];
    const float* W2_0 = (const float*)d_in[6];
    const float* W2_1 = (const float*)d_in[7];
    const float* W2_2 = (const float*)d_in[8];
    const float* b2   = (const float*)d_in[9];
    float* out = (float*)d_out;

    const int N = in_sizes[0] / 480;
    const int nct = (N + 127) / 128;

    prep_kernel<<<160, 256>>>(W1_0, W1_1, W1_2, W2_0, W2_1, W2_2);
    cudaFuncSetAttribute(ffn_hmma, cudaFuncAttributeMaxDynamicSharedMemorySize, SM_TOT);
    ffn_hmma<<<nct, THREADS, SM_TOT>>>(X, attr, b1, b2, out, N);
}

// round 7
// speedup vs baseline: 4.7374x; 1.0955x over previous
#include <cuda_runtime.h>
#include <cuda_bf16.h>
#include <cstdint>
#include <math.h>

// ============================================================================
// Equiformer FFN, warp mma.sync m16n8k16 bf16 hi/lo 3-term split, fp32 acc.
// All operands pre-split to bf16 hi/lo in global (prep kernels); main kernel
// stages everything with cp.async, double-buffers, and fuses mid->out in smem.
// 512 threads = 16 warps; every phase = exactly 16 warp tiles.
// ============================================================================

#define THREADS 512
#define MAXCTA  782

// ---- pre-split weights (prep1), layouts noted ----
#define OFF10 0        // [672 n][136 kpad]  (3 chunks of 224 n contiguous)
#define OFF11 91392    // [192 n][72]
#define OFF12 105216   // [96 n][40]
#define OFF20 109056   // 4 chunks: [kc][128 n][104]  (K=96 per chunk)
#define OFF21 162304   // [64 n][200]
#define OFF22 175104   // [32 n][104]
#define WTOT  178432
__device__ __align__(16) uint16_t g_wh[WTOT];
__device__ __align__(16) uint16_t g_wl[WTOT];

// ---- pre-split X (prep2): per-CTA block of 70656 elems ----
//  [0,17408)            stage1 A  [128 r][136]
//  [17408 + i*9216)     X1_i      [128 r][72]   i<3
//  [45056 + i*5120)     X2_i      [128 r][40]   i<5
#define XBLK 70656
__device__ __align__(16) uint16_t g_xh[(size_t)MAXCTA * XBLK];
__device__ __align__(16) uint16_t g_xl[(size_t)MAXCTA * XBLK];

// ---- scalars (hi/lo, [128 r][392 pad]) + gates fp32 [128 r][288] ----
__device__ __align__(16) uint16_t g_scH[(size_t)MAXCTA * 50176];
__device__ __align__(16) uint16_t g_scL[(size_t)MAXCTA * 50176];
__device__ __align__(16) float    g_gate[(size_t)MAXCTA * 36864];

#define SM_TOT 231936

__device__ __forceinline__ uint32_t s2u(const void* p) {
    uint32_t a;
    asm("{ .reg .u64 t; cvta.to.shared.u64 t, %1; cvt.u32.u64 %0, t; }" : "=r"(a) : "l"(p));
    return a;
}
__device__ __forceinline__ void ldm_x4(uint32_t d[4], uint32_t a) {
    asm volatile("ldmatrix.sync.aligned.m8n8.x4.shared.b16 {%0,%1,%2,%3}, [%4];"
                 : "=r"(d[0]), "=r"(d[1]), "=r"(d[2]), "=r"(d[3]) : "r"(a));
}
__device__ __forceinline__ void ldm_x2(uint32_t d[2], uint32_t a) {
    asm volatile("ldmatrix.sync.aligned.m8n8.x2.shared.b16 {%0,%1}, [%2];"
                 : "=r"(d[0]), "=r"(d[1]) : "r"(a));
}
__device__ __forceinline__ void mma_bf(float (&c)[4], const uint32_t (&a)[4],
                                       const uint32_t (&b)[2]) {
    asm volatile("mma.sync.aligned.m16n8k16.row.col.f32.bf16.bf16.f32 "
                 "{%0,%1,%2,%3},{%4,%5,%6,%7},{%8,%9},{%0,%1,%2,%3};"
                 : "+f"(c[0]), "+f"(c[1]), "+f"(c[2]), "+f"(c[3])
                 : "r"(a[0]), "r"(a[1]), "r"(a[2]), "r"(a[3]), "r"(b[0]), "r"(b[1]));
}
__device__ __forceinline__ void split(float v, uint16_t& h, uint16_t& l) {
    const __nv_bfloat16 hb = __float2bfloat16_rn(v);
    h = __bfloat16_as_ushort(hb);
    l = __bfloat16_as_ushort(__float2bfloat16_rn(v - __bfloat162float(hb)));
}
__device__ __forceinline__ void st_pair(uint16_t* bH, uint16_t* bL, int idx,
                                        float v0, float v1) {
    uint16_t h0, l0, h1, l1;
    split(v0, h0, l0);
    split(v1, h1, l1);
    *reinterpret_cast<uint32_t*>(bH + idx) = (uint32_t)h0 | ((uint32_t)h1 << 16);
    *reinterpret_cast<uint32_t*>(bL + idx) = (uint32_t)l0 | ((uint32_t)l1 << 16);
}
__device__ __forceinline__ void cp16(uint32_t dst, const void* src) {
    asm volatile("cp.async.cg.shared.global [%0], [%1], 16;" :: "r"(dst), "l"(src));
}
#define CP_COMMIT() asm volatile("cp.async.commit_group;" ::: "memory")
#define CP_WAIT()   asm volatile("cp.async.wait_group 0;" ::: "memory")

__device__ __forceinline__ void cpy2(uint32_t dH, uint32_t dL,
                                     const uint16_t* sH, const uint16_t* sL, int elems) {
    const int n16 = elems >> 3;
    for (int i = threadIdx.x; i < n16; i += THREADS) {
        cp16(dH + i * 16, sH + i * 8);
        cp16(dL + i * 16, sL + i * 8);
    }
}
// scalars: 128 rows x 12 chunks of 16B from [r][392] at col offset kcOff
__device__ __forceinline__ void cpy_sc(uint32_t dH, uint32_t dL,
                                       const uint16_t* sH, const uint16_t* sL, int kcOff) {
    for (int i = threadIdx.x; i < 1536; i += THREADS) {
        const int r = i / 12, ch = i - r * 12;
        const uint32_t d = r * 208 + ch * 16;
        const int s = r * 392 + kcOff + ch * 8;
        cp16(dH + d, sH + s);
        cp16(dL + d, sL + s);
    }
}

template <int NTW>
__device__ __forceinline__ void zacc(float (&acc)[2][NTW][4]) {
#pragma unroll
    for (int m = 0; m < 2; m++)
#pragma unroll
        for (int j = 0; j < NTW; j++)
#pragma unroll
            for (int q = 0; q < 4; q++) acc[m][j][q] = 0.0f;
}

template <int KT, int NTW>
__device__ __forceinline__ void mma_tile(uint32_t uAH, uint32_t uAL, uint32_t uBH,
                                         uint32_t uBL, int Kpad, int rowBase, int n8Base,
                                         int lane, float (&acc)[2][NTW][4]) {
    const int ar  = rowBase + (lane & 15);
    const int ak8 = (lane >> 4) * 8;
    const int bn  = lane & 7;
    const int bk8 = ((lane >> 3) & 1) * 8;
#pragma unroll 1
    for (int kt = 0; kt < KT; kt++) {
        const int kb = kt * 16;
        uint32_t Ah[2][4], Al[2][4];
#pragma unroll
        for (int m = 0; m < 2; m++) {
            const uint32_t off = (uint32_t)(((ar + m * 16) * Kpad + kb + ak8) * 2);
            ldm_x4(Ah[m], uAH + off);
            ldm_x4(Al[m], uAL + off);
        }
#pragma unroll
        for (int j = 0; j < NTW; j++) {
            const uint32_t boff =
                (uint32_t)((((n8Base + j) * 8 + bn) * Kpad + kb + bk8) * 2);
            uint32_t Bh[2], Bl[2];
            ldm_x2(Bh, uBH + boff);
            ldm_x2(Bl, uBL + boff);
#pragma unroll
            for (int m = 0; m < 2; m++) {
                mma_bf(acc[m][j], Ah[m], Bh);
                mma_bf(acc[m][j], Ah[m], Bl);
                mma_bf(acc[m][j], Al[m], Bh);
            }
        }
    }
}

// ---- prep1: weights -> hi/lo fragments-ready layouts ----
__device__ __forceinline__ void prep_w(const float* __restrict__ W, int K, int N,
                                       int Kpad, int base) {
    const int tot = K * N;
    for (int idx = blockIdx.x * blockDim.x + threadIdx.x; idx < tot;
         idx += gridDim.x * blockDim.x) {
        const int k = idx / N, n = idx - k * N;
        uint16_t h, l;
        split(__ldg(&W[idx]), h, l);
        g_wh[base + n * Kpad + k] = h;
        g_wl[base + n * Kpad + k] = l;
    }
}
__global__ void prep1(const float* W1_0, const float* W1_1, const float* W1_2,
                      const float* W2_0, const float* W2_1, const float* W2_2) {
    prep_w(W1_0, 128, 672, 136, OFF10);
    prep_w(W1_1, 64, 192, 72, OFF11);
    prep_w(W1_2, 32, 96, 40, OFF12);
    for (int idx = blockIdx.x * blockDim.x + threadIdx.x; idx < 384 * 128;
         idx += gridDim.x * blockDim.x) {
        const int k = idx / 128, n = idx - k * 128;
        const int kc = k / 96, kk = k - kc * 96;
        uint16_t h, l;
        split(__ldg(&W2_0[idx]), h, l);
        g_wh[OFF20 + kc * 13312 + n * 104 + kk] = h;
        g_wl[OFF20 + kc * 13312 + n * 104 + kk] = l;
    }
    prep_w(W2_1, 192, 64, 200, OFF21);
    prep_w(W2_2, 96, 32, 104, OFF22);
}

// ---- prep2: X -> per-CTA hi/lo A layouts ----
__global__ void prep2(const float* __restrict__ X, int Nn, int nct) {
    const size_t tot = (size_t)nct * 128 * 480;
    for (size_t idx = (size_t)blockIdx.x * blockDim.x + threadIdx.x; idx < tot;
         idx += (size_t)gridDim.x * blockDim.x) {
        const int node = (int)(idx / 480), col = (int)(idx - (size_t)node * 480);
        const int r = node & 127, cta = node >> 7;
        const float v = __ldg(&X[(size_t)min(node, Nn - 1) * 480 + col]);
        uint16_t h, l;
        split(v, h, l);
        size_t off;
        const size_t base = (size_t)cta * XBLK;
        if (col < 128) off = base + r * 136 + col;
        else if (col < 320) {
            const int c = col - 128, k = c / 3, i = c - k * 3;
            off = base + 17408 + i * 9216 + r * 72 + k;
        } else {
            const int c = col - 320, k = c / 5, i = c - k * 5;
            off = base + 45056 + i * 5120 + r * 40 + k;
        }
        g_xh[off] = h;
        g_xl[off] = l;
    }
}

__global__ void __launch_bounds__(THREADS, 1)
ffn_main(const float* __restrict__ attr, const float* __restrict__ b1,
         const float* __restrict__ b2, float* __restrict__ out, int Nn) {
    extern __shared__ char smem[];
    float* sAttr = (float*)smem;
    const uint32_t sb = s2u(smem);
    const int tid = threadIdx.x, lane = tid & 31, w = tid >> 5;
    const int g = lane >> 2, t2 = lane & 3;
    const size_t cta = blockIdx.x;
    const int nbase = (int)cta * 128;
    const uint16_t* xh = g_xh + cta * XBLK;
    const uint16_t* xl = g_xl + cta * XBLK;
    uint16_t* scH = g_scH + cta * 50176;
    uint16_t* scL = g_scL + cta * 50176;
    float* gate = g_gate + cta * 36864;

    const float I10 = 0.08838834764831843f, I11 = 0.125f, I12 = 0.17677669529663687f;
    const float I20 = 0.05103103630798288f, I21 = 0.07216878364870323f,
                I22 = 0.10206207261596577f;

    // startup: stage1 A + B chunk 0
    cpy2(sb + 512, sb + 35328, xh, xl, 17408);
    cpy2(sb + 70144, sb + 131072, g_wh + OFF10, g_wl + OFF10, 30464);
    CP_COMMIT();
    if (tid < 128) sAttr[tid] = attr[min(nbase + tid, Nn - 1)];

    // ===== P0: h0 = x0 @ W1_0 (3 N-chunks of 224) =====
    {
        const int mt = w & 3, nt = w >> 2;
        for (int ch = 0; ch < 3; ch++) {
            CP_WAIT();
            __syncthreads();
            float acc[2][7][4];
            zacc<7>(acc);
            mma_tile<8, 7>(sb + 512, sb + 35328, sb + 70144, sb + 131072, 136,
                           mt * 32, nt * 7, lane, acc);
            __syncthreads();
            if (ch < 2) {
                cpy2(sb + 70144, sb + 131072, g_wh + OFF10 + (ch + 1) * 30464,
                     g_wl + OFF10 + (ch + 1) * 30464, 30464);
                CP_COMMIT();
            }
#pragma unroll
            for (int m = 0; m < 2; m++) {
                const int r0 = mt * 32 + m * 16 + g;
#pragma unroll
                for (int j = 0; j < 7; j++) {
                    const int gc = ch * 224 + (nt * 7 + j) * 8 + t2 * 2;
                    const float bb0 = __ldg(&b1[gc]), bb1 = __ldg(&b1[gc + 1]);
#pragma unroll
                    for (int h2 = 0; h2 < 2; h2++) {
                        const int r = r0 + h2 * 8;
                        const float a = sAttr[r] * I10;
                        float x0 = acc[m][j][h2 * 2] * a + bb0;
                        float x1 = acc[m][j][h2 * 2 + 1] * a + bb1;
                        const float s0 = 1.0f / (1.0f + __expf(-x0));
                        const float s1 = 1.0f / (1.0f + __expf(-x1));
                        if (gc < 384) {
                            st_pair(scH, scL, r * 392 + gc, x0 * s0, x1 * s1);
                        } else {
                            *reinterpret_cast<float2*>(gate + r * 288 + gc - 384) =
                                make_float2(s0, s1);
                        }
                    }
                }
            }
        }
    }
    __syncthreads();

    // ===== P1: out0 = scalars @ W2_0 (4 K-chunks of 96, double-buffered) =====
    cpy_sc(sb + 512, sb + 27136, scH, scL, 0);
    cpy2(sb + 107008, sb + 133632, g_wh + OFF20, g_wl + OFF20, 13312);
    CP_COMMIT();
    {
        const int mt = w >> 2, nt = w & 3;
        const uint32_t aHi[2] = {sb + 512, sb + 53760};
        const uint32_t aLo[2] = {sb + 27136, sb + 80384};
        const uint32_t bHi[2] = {sb + 107008, sb + 160256};
        const uint32_t bLo[2] = {sb + 133632, sb + 186880};
        float acc[2][4][4];
        zacc<4>(acc);
        for (int kc = 0; kc < 4; kc++) {
            const int s = kc & 1;
            CP_WAIT();
            __syncthreads();
            if (kc < 3) {
                cpy_sc(aHi[1 - s], aLo[1 - s], scH, scL, (kc + 1) * 96);
                cpy2(bHi[1 - s], bLo[1 - s], g_wh + OFF20 + (kc + 1) * 13312,
                     g_wl + OFF20 + (kc + 1) * 13312, 13312);
                CP_COMMIT();
            }
            mma_tile<6, 4>(aHi[s], aLo[s], bHi[s], bLo[s], 104, mt * 32, nt * 4,
                           lane, acc);
        }
        __syncthreads();
        // P2 initial copies overlap out0 epilogue
        cpy2(sb + 512, sb + 18944, xh + 17408, xl + 17408, 9216);
        cpy2(sb + 37376, sb + 65024, g_wh + OFF11, g_wl + OFF11, 13824);
        CP_COMMIT();
#pragma unroll
        for (int m = 0; m < 2; m++) {
            const int r0 = mt * 32 + m * 16 + g;
#pragma unroll
            for (int j = 0; j < 4; j++) {
                const int c = (nt * 4 + j) * 8 + t2 * 2;
                const float bb0 = __ldg(&b2[c]), bb1 = __ldg(&b2[c + 1]);
#pragma unroll
                for (int h2 = 0; h2 < 2; h2++) {
                    const int r = r0 + h2 * 8, node = nbase + r;
                    if (node < Nn) {
                        const float a = sAttr[r] * I20;
                        *reinterpret_cast<float2*>(out + (size_t)node * 480 + c) =
                            make_float2(acc[m][j][h2 * 2] * a + bb0,
                                        acc[m][j][h2 * 2 + 1] * a + bb1);
                    }
                }
            }
        }
    }

    // ===== P2: mid1_i -> out1_i fused (i=0..2) =====
    {
        const int mt = w >> 2, nt = w & 3;
        const uint32_t xaHi[2] = {sb + 512, sb + 195072};
        const uint32_t xaLo[2] = {sb + 18944, sb + 213504};
        uint16_t* mH = (uint16_t*)(smem + 92672);
        uint16_t* mL = (uint16_t*)(smem + 143872);
        for (int i = 0; i < 3; i++) {
            const int s = i & 1;
            CP_WAIT();
            __syncthreads();
            float acc[2][6][4];
            zacc<6>(acc);
            mma_tile<4, 6>(xaHi[s], xaLo[s], sb + 37376, sb + 65024, 72,
                           mt * 32, nt * 6, lane, acc);
            __syncthreads();
            cpy2(sb + 37376, sb + 62976, g_wh + OFF21, g_wl + OFF21, 12800);
            if (i < 2)
                cpy2(xaHi[1 - s], xaLo[1 - s], xh + 17408 + (i + 1) * 9216,
                     xl + 17408 + (i + 1) * 9216, 9216);
            CP_COMMIT();
#pragma unroll
            for (int m = 0; m < 2; m++) {
                const int r0 = mt * 32 + m * 16 + g;
#pragma unroll
                for (int j = 0; j < 6; j++) {
                    const int c = (nt * 6 + j) * 8 + t2 * 2;
#pragma unroll
                    for (int h2 = 0; h2 < 2; h2++) {
                        const int r = r0 + h2 * 8;
                        const float a = sAttr[r] * I11;
                        const float2 gg =
                            *reinterpret_cast<const float2*>(gate + r * 288 + c);
                        st_pair(mH, mL, r * 200 + c, acc[m][j][h2 * 2] * a * gg.x,
                                acc[m][j][h2 * 2 + 1] * a * gg.y);
                    }
                }
            }
            CP_WAIT();
            __syncthreads();
            float acc2[2][2][4];
            zacc<2>(acc2);
            mma_tile<12, 2>(sb + 92672, sb + 143872, sb + 37376, sb + 62976, 200,
                            mt * 32, nt * 2, lane, acc2);
            __syncthreads();
            if (i < 2) {
                cpy2(sb + 37376, sb + 65024, g_wh + OFF11, g_wl + OFF11, 13824);
                CP_COMMIT();
            }
#pragma unroll
            for (int m = 0; m < 2; m++) {
                const int r0 = mt * 32 + m * 16 + g;
#pragma unroll
                for (int j = 0; j < 2; j++) {
                    const int c = (nt * 2 + j) * 8 + t2 * 2;
#pragma unroll
                    for (int h2 = 0; h2 < 2; h2++) {
                        const int r = r0 + h2 * 8, node = nbase + r;
                        if (node < Nn) {
                            const float a = sAttr[r] * I21;
                            out[(size_t)node * 480 + 128 + c * 3 + i] =
                                acc2[m][j][h2 * 2] * a;
                            out[(size_t)node * 480 + 128 + (c + 1) * 3 + i] =
                                acc2[m][j][h2 * 2 + 1] * a;
                        }
                    }
                }
            }
        }
    }
    __syncthreads();

    // ===== P3: mid2_i -> out2_i fused (i=0..4) =====
    cpy2(sb + 512, sb + 8192, g_wh + OFF12, g_wl + OFF12, 3840);
    cpy2(sb + 15872, sb + 22528, g_wh + OFF22, g_wl + OFF22, 3328);
    cpy2(sb + 82432, sb + 92672, xh + 45056, xl + 45056, 5120);
    CP_COMMIT();
    {
        const int mt = w >> 2, nt = w & 3;
        const uint32_t xaHi[2] = {sb + 82432, sb + 102912};
        const uint32_t xaLo[2] = {sb + 92672, sb + 113152};
        uint16_t* mH = (uint16_t*)(smem + 29184);
        uint16_t* mL = (uint16_t*)(smem + 55808);
        for (int i = 0; i < 5; i++) {
            const int s = i & 1;
            CP_WAIT();
            __syncthreads();
            float acc[2][3][4];
            zacc<3>(acc);
            mma_tile<2, 3>(xaHi[s], xaLo[s], sb + 512, sb + 8192, 40,
                           mt * 32, nt * 3, lane, acc);
            if (i < 4) {
                cpy2(xaHi[1 - s], xaLo[1 - s], xh + 45056 + (i + 1) * 5120,
                     xl + 45056 + (i + 1) * 5120, 5120);
                CP_COMMIT();
            }
#pragma unroll
            for (int m = 0; m < 2; m++) {
                const int r0 = mt * 32 + m * 16 + g;
#pragma unroll
                for (int j = 0; j < 3; j++) {
                    const int c = (nt * 3 + j) * 8 + t2 * 2;
#pragma unroll
                    for (int h2 = 0; h2 < 2; h2++) {
                        const int r = r0 + h2 * 8;
                        const float a = sAttr[r] * I12;
                        const float2 gg = *reinterpret_cast<const float2*>(
                            gate + r * 288 + 192 + c);
                        st_pair(mH, mL, r * 104 + c, acc[m][j][h2 * 2] * a * gg.x,
                                acc[m][j][h2 * 2 + 1] * a * gg.y);
                    }
                }
            }
            __syncthreads();
            float acc2[2][1][4];
            zacc<1>(acc2);
            mma_tile<6, 1>(sb + 29184, sb + 55808, sb + 15872, sb + 22528, 104,
                           mt * 32, nt, lane, acc2);
            __syncthreads();
#pragma unroll
            for (int m = 0; m < 2; m++) {
                const int r0 = mt * 32 + m * 16 + g;
                const int c = nt * 8 + t2 * 2;
#pragma unroll
                for (int h2 = 0; h2 < 2; h2++) {
                    const int r = r0 + h2 * 8, node = nbase + r;
                    if (node < Nn) {
                        const float a = sAttr[r] * I22;
                        out[(size_t)node * 480 + 320 + c * 5 + i] =
                            acc2[m][0][h2 * 2] * a;
                        out[(size_t)node * 480 + 320 + (c + 1) * 5 + i] =
                            acc2[m][0][h2 * 2 + 1] * a;
                    }
                }
            }
        }
    }
}

extern "C" void kernel_launch(void* const* d_in, const int* in_sizes, int n_in,
                              void* d_out, int out_size) {
    const float* X    = (const float*)d_in[0];
    const float* attr = (const float*)d_in[1];
    const float* W1_0 = (const float*)d_in[2];
    const float* W1_1 = (const float*)d_in[3];
    const float* W1_2 = (const float*)d_in[4];
    const float* b1   = (const float*)d_in[5];
    const float* W2_0 = (const float*)d_in[6];
    const float* W2_1 = (const float*)d_in[7];
    const float* W2_2 = (const float*)d_in[8];
    const float* b2   = (const float*)d_in[9];
    float* out = (float*)d_out;

    const int N = in_sizes[0] / 480;
    int nct = (N + 127) / 128;
    if (nct > MAXCTA) nct = MAXCTA;

    prep1<<<160, 256>>>(W1_0, W1_1, W1_2, W2_0, W2_1, W2_2);
    prep2<<<1184, 256>>>(X, N, nct);
    cudaFuncSetAttribute(ffn_main, cudaFuncAttributeMaxDynamicSharedMemorySize, SM_TOT);
    ffn_main<<<nct, THREADS, SM_TOT>>>(attr, b1, b2, out, N);
}

// round 8
// speedup vs baseline: 5.4232x; 1.1448x over previous
#include <cuda_runtime.h>
#include <cuda_bf16.h>
#include <cstdint>
#include <math.h>

// ============================================================================
// Equiformer FFN, warp mma.sync m16n8k16 bf16 hi/lo 3-term split, fp32 acc.
// CTA = 64 nodes, 256 threads (8 warps, 2m x 4n), <=100.4KB smem =>
// 2 CTAs/SM co-resident to hide phase latency. All operands pre-split bf16
// hi/lo in global (prep kernels), staged with cp.async.
// ============================================================================

#define THREADS 256
#define NW      8
#define MAXCTA  1563

// ---- pre-split weights ----
#define OFF10 0        // [672 n][136]  (7 chunks of 96 n contiguous)
#define OFF11 91392    // [192 n][72]   (2 chunks of 96 n contiguous)
#define OFF12 105216   // [96 n][40]
#define OFF20 109056   // 4 x [128 n][104]  (K chunks of 96)
#define OFF21 162304   // 2 x [64 n][104]   (K chunks of 96)
#define OFF22 175616   // [32 n][104]       (K=96)
#define WTOT  178944
__device__ __align__(16) uint16_t g_wh[WTOT];
__device__ __align__(16) uint16_t g_wl[WTOT];

// ---- pre-split X per 64-node CTA ----
//  [0,8704)           stage1 A [64 r][136]
//  [8704 + i*4608)    X1_i [64 r][72]  i<3
//  [22528 + i*2560)   X2_i [64 r][40]  i<5
#define XBLK 35328
__device__ __align__(16) uint16_t g_xh[(size_t)MAXCTA * XBLK];
__device__ __align__(16) uint16_t g_xl[(size_t)MAXCTA * XBLK];

// ---- scalars hi/lo [64 r][392] + gates fp32 [64 r][288] ----
__device__ __align__(16) uint16_t g_scH[(size_t)MAXCTA * 25088];
__device__ __align__(16) uint16_t g_scL[(size_t)MAXCTA * 25088];
__device__ __align__(16) float    g_gate[(size_t)MAXCTA * 18432];

#define SM_TOT 100352

__device__ __forceinline__ uint32_t s2u(const void* p) {
    uint32_t a;
    asm("{ .reg .u64 t; cvta.to.shared.u64 t, %1; cvt.u32.u64 %0, t; }" : "=r"(a) : "l"(p));
    return a;
}
__device__ __forceinline__ void ldm_x4(uint32_t d[4], uint32_t a) {
    asm volatile("ldmatrix.sync.aligned.m8n8.x4.shared.b16 {%0,%1,%2,%3}, [%4];"
                 : "=r"(d[0]), "=r"(d[1]), "=r"(d[2]), "=r"(d[3]) : "r"(a));
}
__device__ __forceinline__ void ldm_x2(uint32_t d[2], uint32_t a) {
    asm volatile("ldmatrix.sync.aligned.m8n8.x2.shared.b16 {%0,%1}, [%2];"
                 : "=r"(d[0]), "=r"(d[1]) : "r"(a));
}
__device__ __forceinline__ void mma_bf(float (&c)[4], const uint32_t (&a)[4],
                                       const uint32_t (&b)[2]) {
    asm volatile("mma.sync.aligned.m16n8k16.row.col.f32.bf16.bf16.f32 "
                 "{%0,%1,%2,%3},{%4,%5,%6,%7},{%8,%9},{%0,%1,%2,%3};"
                 : "+f"(c[0]), "+f"(c[1]), "+f"(c[2]), "+f"(c[3])
                 : "r"(a[0]), "r"(a[1]), "r"(a[2]), "r"(a[3]), "r"(b[0]), "r"(b[1]));
}
__device__ __forceinline__ void split(float v, uint16_t& h, uint16_t& l) {
    const __nv_bfloat16 hb = __float2bfloat16_rn(v);
    h = __bfloat16_as_ushort(hb);
    l = __bfloat16_as_ushort(__float2bfloat16_rn(v - __bfloat162float(hb)));
}
__device__ __forceinline__ void st_pair(uint16_t* bH, uint16_t* bL, int idx,
                                        float v0, float v1) {
    uint16_t h0, l0, h1, l1;
    split(v0, h0, l0);
    split(v1, h1, l1);
    *reinterpret_cast<uint32_t*>(bH + idx) = (uint32_t)h0 | ((uint32_t)h1 << 16);
    *reinterpret_cast<uint32_t*>(bL + idx) = (uint32_t)l0 | ((uint32_t)l1 << 16);
}
__device__ __forceinline__ void cp16(uint32_t dst, const void* src) {
    asm volatile("cp.async.cg.shared.global [%0], [%1], 16;" :: "r"(dst), "l"(src));
}
#define CP_COMMIT() asm volatile("cp.async.commit_group;" ::: "memory")
#define CP_WAIT()   asm volatile("cp.async.wait_group 0;" ::: "memory")

__device__ __forceinline__ void cpy2(uint32_t dH, uint32_t dL,
                                     const uint16_t* sH, const uint16_t* sL, int elems) {
    const int n16 = elems >> 3;
    for (int i = threadIdx.x; i < n16; i += THREADS) {
        cp16(dH + i * 16, sH + i * 8);
        cp16(dL + i * 16, sL + i * 8);
    }
}
// scalars: 64 rows x 12 chunks of 16B from [r][392] at col kcOff -> [r][104]
__device__ __forceinline__ void cpy_sc(uint32_t dH, uint32_t dL,
                                       const uint16_t* sH, const uint16_t* sL, int kcOff) {
    for (int i = threadIdx.x; i < 768; i += THREADS) {
        const int r = i / 12, ch = i - r * 12;
        const uint32_t d = r * 208 + ch * 16;
        const int s = r * 392 + kcOff + ch * 8;
        cp16(dH + d, sH + s);
        cp16(dL + d, sL + s);
    }
}

template <int NTW>
__device__ __forceinline__ void zacc(float (&acc)[2][NTW][4]) {
#pragma unroll
    for (int m = 0; m < 2; m++)
#pragma unroll
        for (int j = 0; j < NTW; j++)
#pragma unroll
            for (int q = 0; q < 4; q++) acc[m][j][q] = 0.0f;
}

template <int KT, int NTW>
__device__ __forceinline__ void mma_tile(uint32_t uAH, uint32_t uAL, uint32_t uBH,
                                         uint32_t uBL, int Kpad, int rowBase, int n8Base,
                                         int lane, float (&acc)[2][NTW][4]) {
    const int ar  = rowBase + (lane & 15);
    const int ak8 = (lane >> 4) * 8;
    const int bn  = lane & 7;
    const int bk8 = ((lane >> 3) & 1) * 8;
#pragma unroll 1
    for (int kt = 0; kt < KT; kt++) {
        const int kb = kt * 16;
        uint32_t Ah[2][4], Al[2][4];
#pragma unroll
        for (int m = 0; m < 2; m++) {
            const uint32_t off = (uint32_t)(((ar + m * 16) * Kpad + kb + ak8) * 2);
            ldm_x4(Ah[m], uAH + off);
            ldm_x4(Al[m], uAL + off);
        }
#pragma unroll
        for (int j = 0; j < NTW; j++) {
            const uint32_t boff =
                (uint32_t)((((n8Base + j) * 8 + bn) * Kpad + kb + bk8) * 2);
            uint32_t Bh[2], Bl[2];
            ldm_x2(Bh, uBH + boff);
            ldm_x2(Bl, uBL + boff);
#pragma unroll
            for (int m = 0; m < 2; m++) {
                mma_bf(acc[m][j], Ah[m], Bh);
                mma_bf(acc[m][j], Ah[m], Bl);
                mma_bf(acc[m][j], Al[m], Bh);
            }
        }
    }
}

// ---- prep1: weights ----
__device__ __forceinline__ void prep_w(const float* __restrict__ W, int K, int N,
                                       int Kpad, int base) {
    const int tot = K * N;
    for (int idx = blockIdx.x * blockDim.x + threadIdx.x; idx < tot;
         idx += gridDim.x * blockDim.x) {
        const int k = idx / N, n = idx - k * N;
        uint16_t h, l;
        split(__ldg(&W[idx]), h, l);
        g_wh[base + n * Kpad + k] = h;
        g_wl[base + n * Kpad + k] = l;
    }
}
__global__ void prep1(const float* W1_0, const float* W1_1, const float* W1_2,
                      const float* W2_0, const float* W2_1, const float* W2_2) {
    prep_w(W1_0, 128, 672, 136, OFF10);
    prep_w(W1_1, 64, 192, 72, OFF11);
    prep_w(W1_2, 32, 96, 40, OFF12);
    for (int idx = blockIdx.x * blockDim.x + threadIdx.x; idx < 384 * 128;
         idx += gridDim.x * blockDim.x) {
        const int k = idx / 128, n = idx - k * 128;
        const int kc = k / 96, kk = k - kc * 96;
        uint16_t h, l;
        split(__ldg(&W2_0[idx]), h, l);
        g_wh[OFF20 + kc * 13312 + n * 104 + kk] = h;
        g_wl[OFF20 + kc * 13312 + n * 104 + kk] = l;
    }
    for (int idx = blockIdx.x * blockDim.x + threadIdx.x; idx < 192 * 64;
         idx += gridDim.x * blockDim.x) {
        const int k = idx / 64, n = idx - k * 64;
        const int kc = k / 96, kk = k - kc * 96;
        uint16_t h, l;
        split(__ldg(&W2_1[idx]), h, l);
        g_wh[OFF21 + kc * 6656 + n * 104 + kk] = h;
        g_wl[OFF21 + kc * 6656 + n * 104 + kk] = l;
    }
    prep_w(W2_2, 96, 32, 104, OFF22);
}

// ---- prep2: X -> per-CTA hi/lo A layouts (64-node blocks) ----
__global__ void prep2(const float* __restrict__ X, int Nn, int nct) {
    const size_t tot = (size_t)nct * 64 * 480;
    for (size_t idx = (size_t)blockIdx.x * blockDim.x + threadIdx.x; idx < tot;
         idx += (size_t)gridDim.x * blockDim.x) {
        const int node = (int)(idx / 480), col = (int)(idx - (size_t)node * 480);
        const int r = node & 63, cta = node >> 6;
        const float v = __ldg(&X[(size_t)min(node, Nn - 1) * 480 + col]);
        uint16_t h, l;
        split(v, h, l);
        size_t off;
        const size_t base = (size_t)cta * XBLK;
        if (col < 128) off = base + r * 136 + col;
        else if (col < 320) {
            const int c = col - 128, k = c / 3, i = c - k * 3;
            off = base + 8704 + i * 4608 + r * 72 + k;
        } else {
            const int c = col - 320, k = c / 5, i = c - k * 5;
            off = base + 22528 + i * 2560 + r * 40 + k;
        }
        g_xh[off] = h;
        g_xl[off] = l;
    }
}

__global__ void __launch_bounds__(THREADS, 2)
ffn_main(const float* __restrict__ attr, const float* __restrict__ b1,
         const float* __restrict__ b2, float* __restrict__ out, int Nn) {
    extern __shared__ char smem[];
    float* sAttr = (float*)smem;
    const uint32_t sb = s2u(smem);
    const int tid = threadIdx.x, lane = tid & 31, w = tid >> 5;
    const int g = lane >> 2, t2 = lane & 3;
    const int mt = w >> 2, nt = w & 3;   // 2m x 4n warp grid
    const size_t cta = blockIdx.x;
    const int nbase = (int)cta * 64;
    const uint16_t* xh = g_xh + cta * XBLK;
    const uint16_t* xl = g_xl + cta * XBLK;
    uint16_t* scH = g_scH + cta * 25088;
    uint16_t* scL = g_scL + cta * 25088;
    float* gate = g_gate + cta * 18432;

    const float I10 = 0.08838834764831843f, I11 = 0.125f, I12 = 0.17677669529663687f;
    const float I20 = 0.05103103630798288f, I21 = 0.07216878364870323f,
                I22 = 0.10206207261596577f;

    // ===== P0: h0 = x0 @ W1_0 (7 N-chunks of 96) =====
    cpy2(sb + 512, sb + 17920, xh, xl, 8704);
    cpy2(sb + 35328, sb + 61440, g_wh + OFF10, g_wl + OFF10, 13056);
    CP_COMMIT();
    if (tid < 64) sAttr[tid] = attr[min(nbase + tid, Nn - 1)];
    for (int ch = 0; ch < 7; ch++) {
        CP_WAIT();
        __syncthreads();
        float acc[2][3][4];
        zacc<3>(acc);
        mma_tile<8, 3>(sb + 512, sb + 17920, sb + 35328, sb + 61440, 136,
                       mt * 32, nt * 3, lane, acc);
        __syncthreads();
        if (ch < 6) {
            cpy2(sb + 35328, sb + 61440, g_wh + OFF10 + (ch + 1) * 13056,
                 g_wl + OFF10 + (ch + 1) * 13056, 13056);
            CP_COMMIT();
        }
#pragma unroll
        for (int m = 0; m < 2; m++) {
            const int r0 = mt * 32 + m * 16 + g;
#pragma unroll
            for (int j = 0; j < 3; j++) {
                const int gc = ch * 96 + (nt * 3 + j) * 8 + t2 * 2;
                const float bb0 = __ldg(&b1[gc]), bb1 = __ldg(&b1[gc + 1]);
#pragma unroll
                for (int h2 = 0; h2 < 2; h2++) {
                    const int r = r0 + h2 * 8;
                    const float a = sAttr[r] * I10;
                    float x0 = acc[m][j][h2 * 2] * a + bb0;
                    float x1 = acc[m][j][h2 * 2 + 1] * a + bb1;
                    const float s0 = 1.0f / (1.0f + __expf(-x0));
                    const float s1 = 1.0f / (1.0f + __expf(-x1));
                    if (gc < 384) {
                        st_pair(scH, scL, r * 392 + gc, x0 * s0, x1 * s1);
                    } else {
                        *reinterpret_cast<float2*>(gate + r * 288 + gc - 384) =
                            make_float2(s0, s1);
                    }
                }
            }
        }
    }
    __syncthreads();

    // ===== P1: out0 = scalars @ W2_0 (4 K-chunks of 96) =====
    {
        cpy_sc(sb + 512, sb + 13824, scH, scL, 0);
        cpy2(sb + 27136, sb + 53760, g_wh + OFF20, g_wl + OFF20, 13312);
        CP_COMMIT();
        float acc[2][4][4];
        zacc<4>(acc);
        for (int kc = 0; kc < 4; kc++) {
            CP_WAIT();
            __syncthreads();
            mma_tile<6, 4>(sb + 512, sb + 13824, sb + 27136, sb + 53760, 104,
                           mt * 32, nt * 4, lane, acc);
            __syncthreads();
            if (kc < 3) {
                cpy_sc(sb + 512, sb + 13824, scH, scL, (kc + 1) * 96);
                cpy2(sb + 27136, sb + 53760, g_wh + OFF20 + (kc + 1) * 13312,
                     g_wl + OFF20 + (kc + 1) * 13312, 13312);
                CP_COMMIT();
            }
        }
#pragma unroll
        for (int m = 0; m < 2; m++) {
            const int r0 = mt * 32 + m * 16 + g;
#pragma unroll
            for (int j = 0; j < 4; j++) {
                const int c = (nt * 4 + j) * 8 + t2 * 2;
                const float bb0 = __ldg(&b2[c]), bb1 = __ldg(&b2[c + 1]);
#pragma unroll
                for (int h2 = 0; h2 < 2; h2++) {
                    const int r = r0 + h2 * 8, node = nbase + r;
                    if (node < Nn) {
                        const float a = sAttr[r] * I20;
                        *reinterpret_cast<float2*>(out + (size_t)node * 480 + c) =
                            make_float2(acc[m][j][h2 * 2] * a + bb0,
                                        acc[m][j][h2 * 2 + 1] * a + bb1);
                    }
                }
            }
        }
    }
    __syncthreads();

    // ===== P2: mid1_i -> out1_i fused, K-split 96+96 (i=0..2) =====
    {
        uint16_t* mH = (uint16_t*)(smem + 46592);
        uint16_t* mL = (uint16_t*)(smem + 59904);
        for (int i = 0; i < 3; i++) {
            cpy2(sb + 512, sb + 9728, xh + 8704 + i * 4608, xl + 8704 + i * 4608, 4608);
            float acc2[2][2][4];
            zacc<2>(acc2);
            for (int kc = 0; kc < 2; kc++) {
                cpy2(sb + 18944, sb + 32768, g_wh + OFF11 + kc * 6912,
                     g_wl + OFF11 + kc * 6912, 6912);
                cpy2(sb + 73216, sb + 86528, g_wh + OFF21 + kc * 6656,
                     g_wl + OFF21 + kc * 6656, 6656);
                CP_COMMIT();
                CP_WAIT();
                __syncthreads();
                float acc[2][3][4];
                zacc<3>(acc);
                mma_tile<4, 3>(sb + 512, sb + 9728, sb + 18944, sb + 32768, 72,
                               mt * 32, nt * 3, lane, acc);
#pragma unroll
                for (int m = 0; m < 2; m++) {
                    const int r0 = mt * 32 + m * 16 + g;
#pragma unroll
                    for (int j = 0; j < 3; j++) {
                        const int c = (nt * 3 + j) * 8 + t2 * 2;
#pragma unroll
                        for (int h2 = 0; h2 < 2; h2++) {
                            const int r = r0 + h2 * 8;
                            const float a = sAttr[r] * I11;
                            const float2 gg = *reinterpret_cast<const float2*>(
                                gate + r * 288 + kc * 96 + c);
                            st_pair(mH, mL, r * 104 + c,
                                    acc[m][j][h2 * 2] * a * gg.x,
                                    acc[m][j][h2 * 2 + 1] * a * gg.y);
                        }
                    }
                }
                __syncthreads();
                mma_tile<6, 2>(sb + 46592, sb + 59904, sb + 73216, sb + 86528, 104,
                               mt * 32, nt * 2, lane, acc2);
                __syncthreads();
            }
#pragma unroll
            for (int m = 0; m < 2; m++) {
                const int r0 = mt * 32 + m * 16 + g;
#pragma unroll
                for (int j = 0; j < 2; j++) {
                    const int c = (nt * 2 + j) * 8 + t2 * 2;
#pragma unroll
                    for (int h2 = 0; h2 < 2; h2++) {
                        const int r = r0 + h2 * 8, node = nbase + r;
                        if (node < Nn) {
                            const float a = sAttr[r] * I21;
                            out[(size_t)node * 480 + 128 + c * 3 + i] =
                                acc2[m][j][h2 * 2] * a;
                            out[(size_t)node * 480 + 128 + (c + 1) * 3 + i] =
                                acc2[m][j][h2 * 2 + 1] * a;
                        }
                    }
                }
            }
        }
    }
    __syncthreads();

    // ===== P3: mid2_i -> out2_i fused (i=0..4) =====
    {
        uint16_t* mH = (uint16_t*)(smem + 26112);
        uint16_t* mL = (uint16_t*)(smem + 39424);
        cpy2(sb + 10752, sb + 18432, g_wh + OFF12, g_wl + OFF12, 3840);
        cpy2(sb + 52736, sb + 59392, g_wh + OFF22, g_wl + OFF22, 3328);
        for (int i = 0; i < 5; i++) {
            cpy2(sb + 512, sb + 5632, xh + 22528 + i * 2560, xl + 22528 + i * 2560, 2560);
            CP_COMMIT();
            CP_WAIT();
            __syncthreads();
            float acc[2][3][4];
            zacc<3>(acc);
            mma_tile<2, 3>(sb + 512, sb + 5632, sb + 10752, sb + 18432, 40,
                           mt * 32, nt * 3, lane, acc);
#pragma unroll
            for (int m = 0; m < 2; m++) {
                const int r0 = mt * 32 + m * 16 + g;
#pragma unroll
                for (int j = 0; j < 3; j++) {
                    const int c = (nt * 3 + j) * 8 + t2 * 2;
#pragma unroll
                    for (int h2 = 0; h2 < 2; h2++) {
                        const int r = r0 + h2 * 8;
                        const float a = sAttr[r] * I12;
                        const float2 gg = *reinterpret_cast<const float2*>(
                            gate + r * 288 + 192 + c);
                        st_pair(mH, mL, r * 104 + c, acc[m][j][h2 * 2] * a * gg.x,
                                acc[m][j][h2 * 2 + 1] * a * gg.y);
                    }
                }
            }
            __syncthreads();
            float acc2[2][1][4];
            zacc<1>(acc2);
            mma_tile<6, 1>(sb + 26112, sb + 39424, sb + 52736, sb + 59392, 104,
                           mt * 32, nt, lane, acc2);
            __syncthreads();
#pragma unroll
            for (int m = 0; m < 2; m++) {
                const int r0 = mt * 32 + m * 16 + g;
                const int c = nt * 8 + t2 * 2;
#pragma unroll
                for (int h2 = 0; h2 < 2; h2++) {
                    const int r = r0 + h2 * 8, node = nbase + r;
                    if (node < Nn) {
                        const float a = sAttr[r] * I22;
                        out[(size_t)node * 480 + 320 + c * 5 + i] = acc2[m][0][h2 * 2] * a;
                        out[(size_t)node * 480 + 320 + (c + 1) * 5 + i] =
                            acc2[m][0][h2 * 2 + 1] * a;
                    }
                }
            }
        }
    }
}

extern "C" void kernel_launch(void* const* d_in, const int* in_sizes, int n_in,
                              void* d_out, int out_size) {
    const float* X    = (const float*)d_in[0];
    const float* attr = (const float*)d_in[1];
    const float* W1_0 = (const float*)d_in[2];
    const float* W1_1 = (const float*)d_in[3];
    const float* W1_2 = (const float*)d_in[4];
    const float* b1   = (const float*)d_in[5];
    const float* W2_0 = (const float*)d_in[6];
    const float* W2_1 = (const float*)d_in[7];
    const float* W2_2 = (const float*)d_in[8];
    const float* b2   = (const float*)d_in[9];
    float* out = (float*)d_out;

    const int N = in_sizes[0] / 480;
    int nct = (N + 63) / 64;
    if (nct > MAXCTA) nct = MAXCTA;

    prep1<<<160, 256>>>(W1_0, W1_1, W1_2, W2_0, W2_1, W2_2);
    prep2<<<1184, 256>>>(X, N, nct);
    cudaFuncSetAttribute(ffn_main, cudaFuncAttributeMaxDynamicSharedMemorySize, SM_TOT);
    ffn_main<<<nct, THREADS, SM_TOT>>>(attr, b1, b2, out, N);
}

// round 9
// speedup vs baseline: 5.4941x; 1.0131x over previous
#include <cuda_runtime.h>
#include <cuda_bf16.h>
#include <cstdint>
#include <math.h>

// ============================================================================
// Equiformer FFN, warp mma.sync m16n8k16 bf16 hi/lo 3-term split, fp32 acc.
// CTA = 64 nodes, 256 threads (8 warps 2m x 4n), 2 CTAs/SM. All cp.async
// copies issued >=1 MMA ahead of their wait (double buffers / prefetch).
// ============================================================================

#define THREADS 256
#define MAXCTA  1563

// ---- pre-split weights ----
#define OFF10 0        // [672 n][136]   (7 chunks of 96 n)
#define OFF11 91392    // [192 n][72]    (2 chunks of 96 n)
#define OFF12 105216   // [96 n][40]
#define OFF20 109056   // 8 x [128 n][56]   (K chunks of 48)
#define OFF21 166400   // 2 x [64 n][104]   (K chunks of 96)
#define OFF22 179712   // [32 n][104]
#define WTOT  183040
__device__ __align__(16) uint16_t g_wh[WTOT];
__device__ __align__(16) uint16_t g_wl[WTOT];

// ---- pre-split X per 64-node CTA ----
#define XBLK 35328
__device__ __align__(16) uint16_t g_xh[(size_t)MAXCTA * XBLK];
__device__ __align__(16) uint16_t g_xl[(size_t)MAXCTA * XBLK];

// ---- scalars hi/lo [64 r][392] + gates fp32 [64 r][288] ----
__device__ __align__(16) uint16_t g_scH[(size_t)MAXCTA * 25088];
__device__ __align__(16) uint16_t g_scL[(size_t)MAXCTA * 25088];
__device__ __align__(16) float    g_gate[(size_t)MAXCTA * 18432];

#define SM_TOT 100352

__device__ __forceinline__ uint32_t s2u(const void* p) {
    uint32_t a;
    asm("{ .reg .u64 t; cvta.to.shared.u64 t, %1; cvt.u32.u64 %0, t; }" : "=r"(a) : "l"(p));
    return a;
}
__device__ __forceinline__ void ldm_x4(uint32_t d[4], uint32_t a) {
    asm volatile("ldmatrix.sync.aligned.m8n8.x4.shared.b16 {%0,%1,%2,%3}, [%4];"
                 : "=r"(d[0]), "=r"(d[1]), "=r"(d[2]), "=r"(d[3]) : "r"(a));
}
__device__ __forceinline__ void ldm_x2(uint32_t d[2], uint32_t a) {
    asm volatile("ldmatrix.sync.aligned.m8n8.x2.shared.b16 {%0,%1}, [%2];"
                 : "=r"(d[0]), "=r"(d[1]) : "r"(a));
}
__device__ __forceinline__ void mma_bf(float (&c)[4], const uint32_t (&a)[4],
                                       const uint32_t (&b)[2]) {
    asm volatile("mma.sync.aligned.m16n8k16.row.col.f32.bf16.bf16.f32 "
                 "{%0,%1,%2,%3},{%4,%5,%6,%7},{%8,%9},{%0,%1,%2,%3};"
                 : "+f"(c[0]), "+f"(c[1]), "+f"(c[2]), "+f"(c[3])
                 : "r"(a[0]), "r"(a[1]), "r"(a[2]), "r"(a[3]), "r"(b[0]), "r"(b[1]));
}
__device__ __forceinline__ void split(float v, uint16_t& h, uint16_t& l) {
    const __nv_bfloat16 hb = __float2bfloat16_rn(v);
    h = __bfloat16_as_ushort(hb);
    l = __bfloat16_as_ushort(__float2bfloat16_rn(v - __bfloat162float(hb)));
}
__device__ __forceinline__ void st_pair(uint16_t* bH, uint16_t* bL, int idx,
                                        float v0, float v1) {
    uint16_t h0, l0, h1, l1;
    split(v0, h0, l0);
    split(v1, h1, l1);
    *reinterpret_cast<uint32_t*>(bH + idx) = (uint32_t)h0 | ((uint32_t)h1 << 16);
    *reinterpret_cast<uint32_t*>(bL + idx) = (uint32_t)l0 | ((uint32_t)l1 << 16);
}
__device__ __forceinline__ void cp16(uint32_t dst, const void* src) {
    asm volatile("cp.async.cg.shared.global [%0], [%1], 16;" :: "r"(dst), "l"(src));
}
#define CP_COMMIT() asm volatile("cp.async.commit_group;" ::: "memory")
#define CP_WAIT0()  asm volatile("cp.async.wait_group 0;" ::: "memory")
#define CP_WAIT1()  asm volatile("cp.async.wait_group 1;" ::: "memory")

__device__ __forceinline__ void cpy2(uint32_t dH, uint32_t dL,
                                     const uint16_t* sH, const uint16_t* sL, int elems) {
    const int n16 = elems >> 3;
    for (int i = threadIdx.x; i < n16; i += THREADS) {
        cp16(dH + i * 16, sH + i * 8);
        cp16(dL + i * 16, sL + i * 8);
    }
}
// scalars: 64 rows x 6 chunks of 16B from [r][392] col kcOff -> [r][56pad]
__device__ __forceinline__ void cpy_sc48(uint32_t dH, uint32_t dL,
                                         const uint16_t* sH, const uint16_t* sL,
                                         int kcOff) {
    for (int i = threadIdx.x; i < 384; i += THREADS) {
        const int r = i / 6, ch = i - r * 6;
        const uint32_t d = r * 112 + ch * 16;
        const int s = r * 392 + kcOff + ch * 8;
        cp16(dH + d, sH + s);
        cp16(dL + d, sL + s);
    }
}

template <int NTW>
__device__ __forceinline__ void zacc(float (&acc)[2][NTW][4]) {
#pragma unroll
    for (int m = 0; m < 2; m++)
#pragma unroll
        for (int j = 0; j < NTW; j++)
#pragma unroll
            for (int q = 0; q < 4; q++) acc[m][j][q] = 0.0f;
}

template <int KT, int NTW>
__device__ __forceinline__ void mma_tile(uint32_t uAH, uint32_t uAL, uint32_t uBH,
                                         uint32_t uBL, int Kpad, int rowBase, int n8Base,
                                         int lane, float (&acc)[2][NTW][4]) {
    const int ar  = rowBase + (lane & 15);
    const int ak8 = (lane >> 4) * 8;
    const int bn  = lane & 7;
    const int bk8 = ((lane >> 3) & 1) * 8;
#pragma unroll 1
    for (int kt = 0; kt < KT; kt++) {
        const int kb = kt * 16;
        uint32_t Ah[2][4], Al[2][4];
#pragma unroll
        for (int m = 0; m < 2; m++) {
            const uint32_t off = (uint32_t)(((ar + m * 16) * Kpad + kb + ak8) * 2);
            ldm_x4(Ah[m], uAH + off);
            ldm_x4(Al[m], uAL + off);
        }
#pragma unroll
        for (int j = 0; j < NTW; j++) {
            const uint32_t boff =
                (uint32_t)((((n8Base + j) * 8 + bn) * Kpad + kb + bk8) * 2);
            uint32_t Bh[2], Bl[2];
            ldm_x2(Bh, uBH + boff);
            ldm_x2(Bl, uBL + boff);
#pragma unroll
            for (int m = 0; m < 2; m++) {
                mma_bf(acc[m][j], Ah[m], Bh);
                mma_bf(acc[m][j], Ah[m], Bl);
                mma_bf(acc[m][j], Al[m], Bh);
            }
        }
    }
}

// ---- merged prep: weights + X ----
__device__ __forceinline__ void prep_w(const float* __restrict__ W, int K, int N,
                                       int Kpad, int base) {
    const int tot = K * N;
    for (int idx = blockIdx.x * blockDim.x + threadIdx.x; idx < tot;
         idx += gridDim.x * blockDim.x) {
        const int k = idx / N, n = idx - k * N;
        uint16_t h, l;
        split(__ldg(&W[idx]), h, l);
        g_wh[base + n * Kpad + k] = h;
        g_wl[base + n * Kpad + k] = l;
    }
}
__global__ void prep(const float* W1_0, const float* W1_1, const float* W1_2,
                     const float* W2_0, const float* W2_1, const float* W2_2,
                     const float* __restrict__ X, int Nn, int nct) {
    prep_w(W1_0, 128, 672, 136, OFF10);
    prep_w(W1_1, 64, 192, 72, OFF11);
    prep_w(W1_2, 32, 96, 40, OFF12);
    for (int idx = blockIdx.x * blockDim.x + threadIdx.x; idx < 384 * 128;
         idx += gridDim.x * blockDim.x) {
        const int k = idx / 128, n = idx - k * 128;
        const int kc = k / 48, kk = k - kc * 48;
        uint16_t h, l;
        split(__ldg(&W2_0[idx]), h, l);
        g_wh[OFF20 + kc * 7168 + n * 56 + kk] = h;
        g_wl[OFF20 + kc * 7168 + n * 56 + kk] = l;
    }
    for (int idx = blockIdx.x * blockDim.x + threadIdx.x; idx < 192 * 64;
         idx += gridDim.x * blockDim.x) {
        const int k = idx / 64, n = idx - k * 64;
        const int kc = k / 96, kk = k - kc * 96;
        uint16_t h, l;
        split(__ldg(&W2_1[idx]), h, l);
        g_wh[OFF21 + kc * 6656 + n * 104 + kk] = h;
        g_wl[OFF21 + kc * 6656 + n * 104 + kk] = l;
    }
    prep_w(W2_2, 96, 32, 104, OFF22);
    // X split
    const size_t tot = (size_t)nct * 64 * 480;
    for (size_t idx = (size_t)blockIdx.x * blockDim.x + threadIdx.x; idx < tot;
         idx += (size_t)gridDim.x * blockDim.x) {
        const int node = (int)(idx / 480), col = (int)(idx - (size_t)node * 480);
        const int r = node & 63, cta = node >> 6;
        const float v = __ldg(&X[(size_t)min(node, Nn - 1) * 480 + col]);
        uint16_t h, l;
        split(v, h, l);
        size_t off;
        const size_t base = (size_t)cta * XBLK;
        if (col < 128) off = base + r * 136 + col;
        else if (col < 320) {
            const int c = col - 128, k = c / 3, i = c - k * 3;
            off = base + 8704 + i * 4608 + r * 72 + k;
        } else {
            const int c = col - 320, k = c / 5, i = c - k * 5;
            off = base + 22528 + i * 2560 + r * 40 + k;
        }
        g_xh[off] = h;
        g_xl[off] = l;
    }
}

__global__ void __launch_bounds__(THREADS, 2)
ffn_main(const float* __restrict__ attr, const float* __restrict__ b1,
         const float* __restrict__ b2, float* __restrict__ out, int Nn) {
    extern __shared__ char smem[];
    float* sAttr = (float*)smem;
    const uint32_t sb = s2u(smem);
    const int tid = threadIdx.x, lane = tid & 31, w = tid >> 5;
    const int g = lane >> 2, t2 = lane & 3;
    const int mt = w >> 2, nt = w & 3;   // 2m x 4n
    const size_t cta = blockIdx.x;
    const int nbase = (int)cta * 64;
    const uint16_t* xh = g_xh + cta * XBLK;
    const uint16_t* xl = g_xl + cta * XBLK;
    uint16_t* scH = g_scH + cta * 25088;
    uint16_t* scL = g_scL + cta * 25088;
    float* gate = g_gate + cta * 18432;

    const float I10 = 0.08838834764831843f, I11 = 0.125f, I12 = 0.17677669529663687f;
    const float I20 = 0.05103103630798288f, I21 = 0.07216878364870323f,
                I22 = 0.10206207261596577f;

    // ===== P0: h0 = x0 @ W1_0 (7 N-chunks of 96) =====
    // A [64x136] at 512/17920; B chunk [96x136] at 35328/61440
    cpy2(sb + 512, sb + 17920, xh, xl, 8704);
    cpy2(sb + 35328, sb + 61440, g_wh + OFF10, g_wl + OFF10, 13056);
    CP_COMMIT();
    if (tid < 64) sAttr[tid] = attr[min(nbase + tid, Nn - 1)];
    for (int ch = 0; ch < 7; ch++) {
        CP_WAIT0();
        __syncthreads();
        float acc[2][3][4];
        zacc<3>(acc);
        mma_tile<8, 3>(sb + 512, sb + 17920, sb + 35328, sb + 61440, 136,
                       mt * 32, nt * 3, lane, acc);
        __syncthreads();
        if (ch < 6) {
            cpy2(sb + 35328, sb + 61440, g_wh + OFF10 + (ch + 1) * 13056,
                 g_wl + OFF10 + (ch + 1) * 13056, 13056);
            CP_COMMIT();
        } else {
            // prefetch P1 chunk 0 (A from scalars cols 0..47, B = W2_0 kc0)
            cpy_sc48(sb + 512, sb + 7680, scH, scL, 0);
            cpy2(sb + 29184, sb + 43520, g_wh + OFF20, g_wl + OFF20, 7168);
            CP_COMMIT();
        }
#pragma unroll
        for (int m = 0; m < 2; m++) {
            const int r0 = mt * 32 + m * 16 + g;
#pragma unroll
            for (int j = 0; j < 3; j++) {
                const int gc = ch * 96 + (nt * 3 + j) * 8 + t2 * 2;
                const float bb0 = __ldg(&b1[gc]), bb1 = __ldg(&b1[gc + 1]);
#pragma unroll
                for (int h2 = 0; h2 < 2; h2++) {
                    const int r = r0 + h2 * 8;
                    const float a = sAttr[r] * I10;
                    float x0 = acc[m][j][h2 * 2] * a + bb0;
                    float x1 = acc[m][j][h2 * 2 + 1] * a + bb1;
                    const float s0 = 1.0f / (1.0f + __expf(-x0));
                    const float s1 = 1.0f / (1.0f + __expf(-x1));
                    if (gc < 384) {
                        st_pair(scH, scL, r * 392 + gc, x0 * s0, x1 * s1);
                    } else {
                        *reinterpret_cast<float2*>(gate + r * 288 + gc - 384) =
                            make_float2(s0, s1);
                    }
                }
            }
        }
        if (ch == 6) __syncthreads();  // scalars/global visible (not needed, safety)
    }

    // ===== P1: out0 = scalars @ W2_0 (8 K-chunks of 48, double-buffered) =====
    {
        const uint32_t aH[2] = {sb + 512, sb + 14848};
        const uint32_t aL[2] = {sb + 7680, sb + 22016};
        const uint32_t bH[2] = {sb + 29184, sb + 57856};
        const uint32_t bL[2] = {sb + 43520, sb + 72192};
        float acc[2][4][4];
        zacc<4>(acc);
        for (int kc = 0; kc < 8; kc++) {
            const int s = kc & 1;
            if (kc < 7) {
                cpy_sc48(aH[1 - s], aL[1 - s], scH, scL, (kc + 1) * 48);
                cpy2(bH[1 - s], bL[1 - s], g_wh + OFF20 + (kc + 1) * 7168,
                     g_wl + OFF20 + (kc + 1) * 7168, 7168);
                CP_COMMIT();
                CP_WAIT1();
            } else {
                CP_WAIT0();
            }
            __syncthreads();
            mma_tile<3, 4>(aH[s], aL[s], bH[s], bL[s], 56, mt * 32, nt * 4, lane, acc);
            __syncthreads();
        }
        // prefetch P2: X1_0 at 512/9728, W1_1 chunk0 at 18944/32768
        cpy2(sb + 512, sb + 9728, xh + 8704, xl + 8704, 4608);
        cpy2(sb + 18944, sb + 32768, g_wh + OFF11, g_wl + OFF11, 6912);
        CP_COMMIT();
        // out0 epilogue
#pragma unroll
        for (int m = 0; m < 2; m++) {
            const int r0 = mt * 32 + m * 16 + g;
#pragma unroll
            for (int j = 0; j < 4; j++) {
                const int c = (nt * 4 + j) * 8 + t2 * 2;
                const float bb0 = __ldg(&b2[c]), bb1 = __ldg(&b2[c + 1]);
#pragma unroll
                for (int h2 = 0; h2 < 2; h2++) {
                    const int r = r0 + h2 * 8, node = nbase + r;
                    if (node < Nn) {
                        const float a = sAttr[r] * I20;
                        *reinterpret_cast<float2*>(out + (size_t)node * 480 + c) =
                            make_float2(acc[m][j][h2 * 2] * a + bb0,
                                        acc[m][j][h2 * 2 + 1] * a + bb1);
                    }
                }
            }
        }
    }

    // ===== P2: mid1_i -> out1_i fused, K-split 96+96 (i=0..2) =====
    // X at 512/9728; W1_1 chunk at 18944/32768; mid at 46592/59904;
    // W2_1 chunk at 73216/86528
    {
        uint16_t* mH = (uint16_t*)(smem + 46592);
        uint16_t* mL = (uint16_t*)(smem + 59904);
        for (int i = 0; i < 3; i++) {
            float acc2[2][2][4];
            zacc<2>(acc2);
            for (int kc = 0; kc < 2; kc++) {
                CP_WAIT0();
                __syncthreads();
                float acc[2][3][4];
                zacc<3>(acc);
                mma_tile<4, 3>(sb + 512, sb + 9728, sb + 18944, sb + 32768, 72,
                               mt * 32, nt * 3, lane, acc);
                __syncthreads();
                // gB: W2_1(kc)
                cpy2(sb + 73216, sb + 86528, g_wh + OFF21 + kc * 6656,
                     g_wl + OFF21 + kc * 6656, 6656);
                CP_COMMIT();
                // gC: prefetch next-iteration inputs
                if (kc == 0) {
                    cpy2(sb + 18944, sb + 32768, g_wh + OFF11 + 6912,
                         g_wl + OFF11 + 6912, 6912);
                } else if (i < 2) {
                    cpy2(sb + 18944, sb + 32768, g_wh + OFF11, g_wl + OFF11, 6912);
                    cpy2(sb + 512, sb + 9728, xh + 8704 + (i + 1) * 4608,
                         xl + 8704 + (i + 1) * 4608, 4608);
                } else {
                    // P3 preload: X2_0, W1_2, W2_2 (into regions free after mid mma)
                    cpy2(sb + 512, sb + 5632, xh + 22528, xl + 22528, 2560);
                    cpy2(sb + 10752, sb + 18432, g_wh + OFF12, g_wl + OFF12, 3840);
                    cpy2(sb + 26112, sb + 32768, g_wh + OFF22, g_wl + OFF22, 3328);
                }
                CP_COMMIT();
                // mid epilogue -> smem
#pragma unroll
                for (int m = 0; m < 2; m++) {
                    const int r0 = mt * 32 + m * 16 + g;
#pragma unroll
                    for (int j = 0; j < 3; j++) {
                        const int c = (nt * 3 + j) * 8 + t2 * 2;
#pragma unroll
                        for (int h2 = 0; h2 < 2; h2++) {
                            const int r = r0 + h2 * 8;
                            const float a = sAttr[r] * I11;
                            const float2 gg = *reinterpret_cast<const float2*>(
                                gate + r * 288 + kc * 96 + c);
                            st_pair(mH, mL, r * 104 + c,
                                    acc[m][j][h2 * 2] * a * gg.x,
                                    acc[m][j][h2 * 2 + 1] * a * gg.y);
                        }
                    }
                }
                __syncthreads();
                CP_WAIT1();   // W2_1(kc) done; gC may pend
                __syncthreads();
                mma_tile<6, 2>(sb + 46592, sb + 59904, sb + 73216, sb + 86528, 104,
                               mt * 32, nt * 2, lane, acc2);
                __syncthreads();
            }
            // out1 epilogue
#pragma unroll
            for (int m = 0; m < 2; m++) {
                const int r0 = mt * 32 + m * 16 + g;
#pragma unroll
                for (int j = 0; j < 2; j++) {
                    const int c = (nt * 2 + j) * 8 + t2 * 2;
#pragma unroll
                    for (int h2 = 0; h2 < 2; h2++) {
                        const int r = r0 + h2 * 8, node = nbase + r;
                        if (node < Nn) {
                            const float a = sAttr[r] * I21;
                            out[(size_t)node * 480 + 128 + c * 3 + i] =
                                acc2[m][j][h2 * 2] * a;
                            out[(size_t)node * 480 + 128 + (c + 1) * 3 + i] =
                                acc2[m][j][h2 * 2 + 1] * a;
                        }
                    }
                }
            }
        }
    }

    // ===== P3: mid2_i -> out2_i fused (i=0..4) =====
    // X at 512/5632; W1_2 at 10752/18432; W2_2 at 26112/32768; mid 46592/59904
    {
        uint16_t* mH = (uint16_t*)(smem + 46592);
        uint16_t* mL = (uint16_t*)(smem + 59904);
        for (int i = 0; i < 5; i++) {
            CP_WAIT0();
            __syncthreads();
            float acc[2][3][4];
            zacc<3>(acc);
            mma_tile<2, 3>(sb + 512, sb + 5632, sb + 10752, sb + 18432, 40,
                           mt * 32, nt * 3, lane, acc);
            __syncthreads();
            if (i < 4) {
                cpy2(sb + 512, sb + 5632, xh + 22528 + (i + 1) * 2560,
                     xl + 22528 + (i + 1) * 2560, 2560);
                CP_COMMIT();
            }
            // mid epilogue -> smem
#pragma unroll
            for (int m = 0; m < 2; m++) {
                const int r0 = mt * 32 + m * 16 + g;
#pragma unroll
                for (int j = 0; j < 3; j++) {
                    const int c = (nt * 3 + j) * 8 + t2 * 2;
#pragma unroll
                    for (int h2 = 0; h2 < 2; h2++) {
                        const int r = r0 + h2 * 8;
                        const float a = sAttr[r] * I12;
                        const float2 gg = *reinterpret_cast<const float2*>(
                            gate + r * 288 + 192 + c);
                        st_pair(mH, mL, r * 104 + c, acc[m][j][h2 * 2] * a * gg.x,
                                acc[m][j][h2 * 2 + 1] * a * gg.y);
                    }
                }
            }
            __syncthreads();
            float acc2[2][1][4];
            zacc<1>(acc2);
            mma_tile<6, 1>(sb + 46592, sb + 59904, sb + 26112, sb + 32768, 104,
                           mt * 32, nt, lane, acc2);
            __syncthreads();
#pragma unroll
            for (int m = 0; m < 2; m++) {
                const int r0 = mt * 32 + m * 16 + g;
                const int c = nt * 8 + t2 * 2;
#pragma unroll
                for (int h2 = 0; h2 < 2; h2++) {
                    const int r = r0 + h2 * 8, node = nbase + r;
                    if (node < Nn) {
                        const float a = sAttr[r] * I22;
                        out[(size_t)node * 480 + 320 + c * 5 + i] =
                            acc2[m][0][h2 * 2] * a;
                        out[(size_t)node * 480 + 320 + (c + 1) * 5 + i] =
                            acc2[m][0][h2 * 2 + 1] * a;
                    }
                }
            }
        }
    }
}

extern "C" void kernel_launch(void* const* d_in, const int* in_sizes, int n_in,
                              void* d_out, int out_size) {
    const float* X    = (const float*)d_in[0];
    const float* attr = (const float*)d_in[1];
    const float* W1_0 = (const float*)d_in[2];
    const float* W1_1 = (const float*)d_in[3];
    const float* W1_2 = (const float*)d_in[4];
    const float* b1   = (const float*)d_in[5];
    const float* W2_0 = (const float*)d_in[6];
    const float* W2_1 = (const float*)d_in[7];
    const float* W2_2 = (const float*)d_in[8];
    const float* b2   = (const float*)d_in[9];
    float* out = (float*)d_out;

    const int N = in_sizes[0] / 480;
    int nct = (N + 63) / 64;
    if (nct > MAXCTA) nct = MAXCTA;

    prep<<<1184, 256>>>(W1_0, W1_1, W1_2, W2_0, W2_1, W2_2, X, N, nct);
    cudaFuncSetAttribute(ffn_main, cudaFuncAttributeMaxDynamicSharedMemorySize, SM_TOT);
    ffn_main<<<nct, THREADS, SM_TOT>>>(attr, b1, b2, out, N);
}

// round 10
// speedup vs baseline: 6.2148x; 1.1312x over previous
#include <cuda_runtime.h>
#include <cuda_bf16.h>
#include <cstdint>
#include <math.h>

// ============================================================================
// Equiformer FFN, warp mma.sync m16n8k16 bf16 hi/lo 3-term split, fp32 acc.
// CTA = 64 nodes, 256 threads (8 warps 2m x 4n), 2 CTAs/SM. Weights pre-split
// in global (tiny prep kernel); X converted in-kernel (vectorized) into smem.
// All cp.async copies issued >=1 MMA ahead of their wait.
// ============================================================================

#define THREADS 256
#define MAXCTA  1563

// ---- pre-split weights ----
#define OFF10 0        // [672 n][136]   (7 chunks of 96 n)
#define OFF11 91392    // [192 n][72]    (2 chunks of 96 n)
#define OFF12 105216   // [96 n][40]
#define OFF20 109056   // 8 x [128 n][56]   (K chunks of 48)
#define OFF21 166400   // 2 x [64 n][104]   (K chunks of 96)
#define OFF22 179712   // [32 n][104]
#define WTOT  183040
__device__ __align__(16) uint16_t g_wh[WTOT];
__device__ __align__(16) uint16_t g_wl[WTOT];

// ---- scalars hi/lo [64 r][392] + gates fp32 [64 r][288] ----
__device__ __align__(16) uint16_t g_scH[(size_t)MAXCTA * 25088];
__device__ __align__(16) uint16_t g_scL[(size_t)MAXCTA * 25088];
__device__ __align__(16) float    g_gate[(size_t)MAXCTA * 18432];

#define SM_TOT 100352

__device__ __forceinline__ uint32_t s2u(const void* p) {
    uint32_t a;
    asm("{ .reg .u64 t; cvta.to.shared.u64 t, %1; cvt.u32.u64 %0, t; }" : "=r"(a) : "l"(p));
    return a;
}
__device__ __forceinline__ void ldm_x4(uint32_t d[4], uint32_t a) {
    asm volatile("ldmatrix.sync.aligned.m8n8.x4.shared.b16 {%0,%1,%2,%3}, [%4];"
                 : "=r"(d[0]), "=r"(d[1]), "=r"(d[2]), "=r"(d[3]) : "r"(a));
}
__device__ __forceinline__ void ldm_x2(uint32_t d[2], uint32_t a) {
    asm volatile("ldmatrix.sync.aligned.m8n8.x2.shared.b16 {%0,%1}, [%2];"
                 : "=r"(d[0]), "=r"(d[1]) : "r"(a));
}
__device__ __forceinline__ void mma_bf(float (&c)[4], const uint32_t (&a)[4],
                                       const uint32_t (&b)[2]) {
    asm volatile("mma.sync.aligned.m16n8k16.row.col.f32.bf16.bf16.f32 "
                 "{%0,%1,%2,%3},{%4,%5,%6,%7},{%8,%9},{%0,%1,%2,%3};"
                 : "+f"(c[0]), "+f"(c[1]), "+f"(c[2]), "+f"(c[3])
                 : "r"(a[0]), "r"(a[1]), "r"(a[2]), "r"(a[3]), "r"(b[0]), "r"(b[1]));
}
__device__ __forceinline__ void split(float v, uint16_t& h, uint16_t& l) {
    const __nv_bfloat16 hb = __float2bfloat16_rn(v);
    h = __bfloat16_as_ushort(hb);
    l = __bfloat16_as_ushort(__float2bfloat16_rn(v - __bfloat162float(hb)));
}
__device__ __forceinline__ void st_pair(uint16_t* bH, uint16_t* bL, int idx,
                                        float v0, float v1) {
    uint16_t h0, l0, h1, l1;
    split(v0, h0, l0);
    split(v1, h1, l1);
    *reinterpret_cast<uint32_t*>(bH + idx) = (uint32_t)h0 | ((uint32_t)h1 << 16);
    *reinterpret_cast<uint32_t*>(bL + idx) = (uint32_t)l0 | ((uint32_t)l1 << 16);
}
__device__ __forceinline__ void cp16(uint32_t dst, const void* src) {
    asm volatile("cp.async.cg.shared.global [%0], [%1], 16;" :: "r"(dst), "l"(src));
}
#define CP_COMMIT() asm volatile("cp.async.commit_group;" ::: "memory")
#define CP_WAIT0()  asm volatile("cp.async.wait_group 0;" ::: "memory")
#define CP_WAIT1()  asm volatile("cp.async.wait_group 1;" ::: "memory")

__device__ __forceinline__ void cpy2(uint32_t dH, uint32_t dL,
                                     const uint16_t* sH, const uint16_t* sL, int elems) {
    const int n16 = elems >> 3;
    for (int i = threadIdx.x; i < n16; i += THREADS) {
        cp16(dH + i * 16, sH + i * 8);
        cp16(dL + i * 16, sL + i * 8);
    }
}
// scalars: 64 rows x 6 chunks of 16B from [r][392] col kcOff -> [r][56pad]
__device__ __forceinline__ void cpy_sc48(uint32_t dH, uint32_t dL,
                                         const uint16_t* sH, const uint16_t* sL,
                                         int kcOff) {
    for (int i = threadIdx.x; i < 384; i += THREADS) {
        const int r = i / 6, ch = i - r * 6;
        const uint32_t d = r * 112 + ch * 16;
        const int s = r * 392 + kcOff + ch * 8;
        cp16(dH + d, sH + s);
        cp16(dL + d, sL + s);
    }
}

// ---- in-kernel X conversion: 8 fp32 -> hi/lo bf16x8, 16B smem stores ----
__device__ __forceinline__ void pack_sts(const float* v, uint32_t dH, uint32_t dL) {
    uint32_t hi[4], lo[4];
#pragma unroll
    for (int q = 0; q < 4; q++) {
        uint16_t h0, l0, h1, l1;
        split(v[2 * q], h0, l0);
        split(v[2 * q + 1], h1, l1);
        hi[q] = (uint32_t)h0 | ((uint32_t)h1 << 16);
        lo[q] = (uint32_t)l0 | ((uint32_t)l1 << 16);
    }
    asm volatile("st.shared.v4.b32 [%0], {%1,%2,%3,%4};"
                 :: "r"(dH), "r"(hi[0]), "r"(hi[1]), "r"(hi[2]), "r"(hi[3]) : "memory");
    asm volatile("st.shared.v4.b32 [%0], {%1,%2,%3,%4};"
                 :: "r"(dL), "r"(lo[0]), "r"(lo[1]), "r"(lo[2]), "r"(lo[3]) : "memory");
}
// l=0 block: contiguous cols 0..127 -> [64 r][136 pad]
__device__ void conv_seg0(uint32_t dH, uint32_t dL, const float* __restrict__ X,
                          int nbase, int Nn) {
    for (int idx = threadIdx.x; idx < 1024; idx += THREADS) {
        const int r = idx >> 4, k8 = idx & 15;
        const float4* p = reinterpret_cast<const float4*>(
            X + (size_t)min(nbase + r, Nn - 1) * 480 + k8 * 8);
        const float4 a = __ldg(&p[0]), b = __ldg(&p[1]);
        const float v[8] = {a.x, a.y, a.z, a.w, b.x, b.y, b.z, b.w};
        pack_sts(v, dH + r * 272 + k8 * 16, dL + r * 272 + k8 * 16);
    }
}
// strided component slice: col = col0 + STRIDE*k -> [64 r][Kpad]
template <int K8, int STRIDE>
__device__ void conv_str(uint32_t dH, uint32_t dL, const float* __restrict__ X,
                         int nbase, int Nn, int col0, int rowB) {
    for (int idx = threadIdx.x; idx < 64 * K8; idx += THREADS) {
        const int r = idx / K8, k8 = idx - r * K8;
        const float* p = X + (size_t)min(nbase + r, Nn - 1) * 480 + col0 +
                         k8 * 8 * STRIDE;
        float v[8];
#pragma unroll
        for (int q = 0; q < 8; q++) v[q] = __ldg(&p[q * STRIDE]);
        pack_sts(v, dH + r * rowB + k8 * 16, dL + r * rowB + k8 * 16);
    }
}

template <int NTW>
__device__ __forceinline__ void zacc(float (&acc)[2][NTW][4]) {
#pragma unroll
    for (int m = 0; m < 2; m++)
#pragma unroll
        for (int j = 0; j < NTW; j++)
#pragma unroll
            for (int q = 0; q < 4; q++) acc[m][j][q] = 0.0f;
}

template <int KT, int NTW>
__device__ __forceinline__ void mma_tile(uint32_t uAH, uint32_t uAL, uint32_t uBH,
                                         uint32_t uBL, int Kpad, int rowBase, int n8Base,
                                         int lane, float (&acc)[2][NTW][4]) {
    const int ar  = rowBase + (lane & 15);
    const int ak8 = (lane >> 4) * 8;
    const int bn  = lane & 7;
    const int bk8 = ((lane >> 3) & 1) * 8;
#pragma unroll 1
    for (int kt = 0; kt < KT; kt++) {
        const int kb = kt * 16;
        uint32_t Ah[2][4], Al[2][4];
#pragma unroll
        for (int m = 0; m < 2; m++) {
            const uint32_t off = (uint32_t)(((ar + m * 16) * Kpad + kb + ak8) * 2);
            ldm_x4(Ah[m], uAH + off);
            ldm_x4(Al[m], uAL + off);
        }
#pragma unroll
        for (int j = 0; j < NTW; j++) {
            const uint32_t boff =
                (uint32_t)((((n8Base + j) * 8 + bn) * Kpad + kb + bk8) * 2);
            uint32_t Bh[2], Bl[2];
            ldm_x2(Bh, uBH + boff);
            ldm_x2(Bl, uBL + boff);
#pragma unroll
            for (int m = 0; m < 2; m++) {
                mma_bf(acc[m][j], Ah[m], Bh);
                mma_bf(acc[m][j], Ah[m], Bl);
                mma_bf(acc[m][j], Al[m], Bh);
            }
        }
    }
}

// ---- prep: weights only ----
__device__ __forceinline__ void prep_w(const float* __restrict__ W, int K, int N,
                                       int Kpad, int base) {
    const int tot = K * N;
    for (int idx = blockIdx.x * blockDim.x + threadIdx.x; idx < tot;
         idx += gridDim.x * blockDim.x) {
        const int k = idx / N, n = idx - k * N;
        uint16_t h, l;
        split(__ldg(&W[idx]), h, l);
        g_wh[base + n * Kpad + k] = h;
        g_wl[base + n * Kpad + k] = l;
    }
}
__global__ void prep(const float* W1_0, const float* W1_1, const float* W1_2,
                     const float* W2_0, const float* W2_1, const float* W2_2) {
    prep_w(W1_0, 128, 672, 136, OFF10);
    prep_w(W1_1, 64, 192, 72, OFF11);
    prep_w(W1_2, 32, 96, 40, OFF12);
    for (int idx = blockIdx.x * blockDim.x + threadIdx.x; idx < 384 * 128;
         idx += gridDim.x * blockDim.x) {
        const int k = idx / 128, n = idx - k * 128;
        const int kc = k / 48, kk = k - kc * 48;
        uint16_t h, l;
        split(__ldg(&W2_0[idx]), h, l);
        g_wh[OFF20 + kc * 7168 + n * 56 + kk] = h;
        g_wl[OFF20 + kc * 7168 + n * 56 + kk] = l;
    }
    for (int idx = blockIdx.x * blockDim.x + threadIdx.x; idx < 192 * 64;
         idx += gridDim.x * blockDim.x) {
        const int k = idx / 64, n = idx - k * 64;
        const int kc = k / 96, kk = k - kc * 96;
        uint16_t h, l;
        split(__ldg(&W2_1[idx]), h, l);
        g_wh[OFF21 + kc * 6656 + n * 104 + kk] = h;
        g_wl[OFF21 + kc * 6656 + n * 104 + kk] = l;
    }
    prep_w(W2_2, 96, 32, 104, OFF22);
}

__global__ void __launch_bounds__(THREADS, 2)
ffn_main(const float* __restrict__ X, const float* __restrict__ attr,
         const float* __restrict__ b1, const float* __restrict__ b2,
         float* __restrict__ out, int Nn) {
    extern __shared__ char smem[];
    float* sAttr = (float*)smem;
    const uint32_t sb = s2u(smem);
    const int tid = threadIdx.x, lane = tid & 31, w = tid >> 5;
    const int g = lane >> 2, t2 = lane & 3;
    const int mt = w >> 2, nt = w & 3;   // 2m x 4n
    const size_t cta = blockIdx.x;
    const int nbase = (int)cta * 64;
    uint16_t* scH = g_scH + cta * 25088;
    uint16_t* scL = g_scL + cta * 25088;
    float* gate = g_gate + cta * 18432;

    const float I10 = 0.08838834764831843f, I11 = 0.125f, I12 = 0.17677669529663687f;
    const float I20 = 0.05103103630798288f, I21 = 0.07216878364870323f,
                I22 = 0.10206207261596577f;

    // ===== P0: h0 = x0 @ W1_0 (7 N-chunks of 96) =====
    // A [64x136] at 512/17920; B chunk [96x136] at 35328/61440
    cpy2(sb + 35328, sb + 61440, g_wh + OFF10, g_wl + OFF10, 13056);
    CP_COMMIT();
    if (tid < 64) sAttr[tid] = attr[min(nbase + tid, Nn - 1)];
    conv_seg0(sb + 512, sb + 17920, X, nbase, Nn);
    for (int ch = 0; ch < 7; ch++) {
        CP_WAIT0();
        __syncthreads();
        float acc[2][3][4];
        zacc<3>(acc);
        mma_tile<8, 3>(sb + 512, sb + 17920, sb + 35328, sb + 61440, 136,
                       mt * 32, nt * 3, lane, acc);
        __syncthreads();
        if (ch < 6) {
            cpy2(sb + 35328, sb + 61440, g_wh + OFF10 + (ch + 1) * 13056,
                 g_wl + OFF10 + (ch + 1) * 13056, 13056);
            CP_COMMIT();
        } else {
            // prefetch P1 chunk 0 (A from scalar cols 0..47, B = W2_0 kc0)
            cpy_sc48(sb + 512, sb + 7680, scH, scL, 0);
            cpy2(sb + 29184, sb + 43520, g_wh + OFF20, g_wl + OFF20, 7168);
            CP_COMMIT();
        }
#pragma unroll
        for (int m = 0; m < 2; m++) {
            const int r0 = mt * 32 + m * 16 + g;
#pragma unroll
            for (int j = 0; j < 3; j++) {
                const int gc = ch * 96 + (nt * 3 + j) * 8 + t2 * 2;
                const float bb0 = __ldg(&b1[gc]), bb1 = __ldg(&b1[gc + 1]);
#pragma unroll
                for (int h2 = 0; h2 < 2; h2++) {
                    const int r = r0 + h2 * 8;
                    const float a = sAttr[r] * I10;
                    float x0 = acc[m][j][h2 * 2] * a + bb0;
                    float x1 = acc[m][j][h2 * 2 + 1] * a + bb1;
                    const float s0 = 1.0f / (1.0f + __expf(-x0));
                    const float s1 = 1.0f / (1.0f + __expf(-x1));
                    if (gc < 384) {
                        st_pair(scH, scL, r * 392 + gc, x0 * s0, x1 * s1);
                    } else {
                        *reinterpret_cast<float2*>(gate + r * 288 + gc - 384) =
                            make_float2(s0, s1);
                    }
                }
            }
        }
        if (ch == 6) __syncthreads();
    }

    // ===== P1: out0 = scalars @ W2_0 (8 K-chunks of 48, double-buffered) =====
    {
        const uint32_t aH[2] = {sb + 512, sb + 14848};
        const uint32_t aL[2] = {sb + 7680, sb + 22016};
        const uint32_t bH[2] = {sb + 29184, sb + 57856};
        const uint32_t bL[2] = {sb + 43520, sb + 72192};
        float acc[2][4][4];
        zacc<4>(acc);
        for (int kc = 0; kc < 8; kc++) {
            const int s = kc & 1;
            if (kc < 7) {
                cpy_sc48(aH[1 - s], aL[1 - s], scH, scL, (kc + 1) * 48);
                cpy2(bH[1 - s], bL[1 - s], g_wh + OFF20 + (kc + 1) * 7168,
                     g_wl + OFF20 + (kc + 1) * 7168, 7168);
                CP_COMMIT();
                CP_WAIT1();
            } else {
                CP_WAIT0();
            }
            __syncthreads();
            mma_tile<3, 4>(aH[s], aL[s], bH[s], bL[s], 56, mt * 32, nt * 4, lane, acc);
            __syncthreads();
        }
        // prefetch P2: W1_1 chunk0 (async) + convert X1_0 in-kernel
        cpy2(sb + 18944, sb + 32768, g_wh + OFF11, g_wl + OFF11, 6912);
        CP_COMMIT();
        conv_str<8, 3>(sb + 512, sb + 9728, X, nbase, Nn, 128, 144);
        // out0 epilogue
#pragma unroll
        for (int m = 0; m < 2; m++) {
            const int r0 = mt * 32 + m * 16 + g;
#pragma unroll
            for (int j = 0; j < 4; j++) {
                const int c = (nt * 4 + j) * 8 + t2 * 2;
                const float bb0 = __ldg(&b2[c]), bb1 = __ldg(&b2[c + 1]);
#pragma unroll
                for (int h2 = 0; h2 < 2; h2++) {
                    const int r = r0 + h2 * 8, node = nbase + r;
                    if (node < Nn) {
                        const float a = sAttr[r] * I20;
                        *reinterpret_cast<float2*>(out + (size_t)node * 480 + c) =
                            make_float2(acc[m][j][h2 * 2] * a + bb0,
                                        acc[m][j][h2 * 2 + 1] * a + bb1);
                    }
                }
            }
        }
    }

    // ===== P2: mid1_i -> out1_i fused, K-split 96+96 (i=0..2) =====
    // X1 at 512/9728; W1_1 chunk at 18944/32768; mid at 46592/59904;
    // W2_1 chunk at 73216/86528
    {
        uint16_t* mH = (uint16_t*)(smem + 46592);
        uint16_t* mL = (uint16_t*)(smem + 59904);
        for (int i = 0; i < 3; i++) {
            float acc2[2][2][4];
            zacc<2>(acc2);
            for (int kc = 0; kc < 2; kc++) {
                CP_WAIT0();
                __syncthreads();
                float acc[2][3][4];
                zacc<3>(acc);
                mma_tile<4, 3>(sb + 512, sb + 9728, sb + 18944, sb + 32768, 72,
                               mt * 32, nt * 3, lane, acc);
                __syncthreads();
                // one group: W2_1(kc) + next W1_1 chunk (or P3 weights)
                cpy2(sb + 73216, sb + 86528, g_wh + OFF21 + kc * 6656,
                     g_wl + OFF21 + kc * 6656, 6656);
                if (kc == 0) {
                    cpy2(sb + 18944, sb + 32768, g_wh + OFF11 + 6912,
                         g_wl + OFF11 + 6912, 6912);
                } else if (i < 2) {
                    cpy2(sb + 18944, sb + 32768, g_wh + OFF11, g_wl + OFF11, 6912);
                } else {
                    cpy2(sb + 10752, sb + 18432, g_wh + OFF12, g_wl + OFF12, 3840);
                    cpy2(sb + 26112, sb + 32768, g_wh + OFF22, g_wl + OFF22, 3328);
                }
                CP_COMMIT();
                // mid epilogue -> smem
#pragma unroll
                for (int m = 0; m < 2; m++) {
                    const int r0 = mt * 32 + m * 16 + g;
#pragma unroll
                    for (int j = 0; j < 3; j++) {
                        const int c = (nt * 3 + j) * 8 + t2 * 2;
#pragma unroll
                        for (int h2 = 0; h2 < 2; h2++) {
                            const int r = r0 + h2 * 8;
                            const float a = sAttr[r] * I11;
                            const float2 gg = *reinterpret_cast<const float2*>(
                                gate + r * 288 + kc * 96 + c);
                            st_pair(mH, mL, r * 104 + c,
                                    acc[m][j][h2 * 2] * a * gg.x,
                                    acc[m][j][h2 * 2 + 1] * a * gg.y);
                        }
                    }
                }
                // convert next X slice while W2_1 copy is in flight
                if (kc == 1) {
                    if (i < 2)
                        conv_str<8, 3>(sb + 512, sb + 9728, X, nbase, Nn,
                                       128 + i + 1, 144);
                    else
                        conv_str<4, 5>(sb + 512, sb + 5632, X, nbase, Nn, 320, 80);
                }
                __syncthreads();
                CP_WAIT0();
                __syncthreads();
                mma_tile<6, 2>(sb + 46592, sb + 59904, sb + 73216, sb + 86528, 104,
                               mt * 32, nt * 2, lane, acc2);
                __syncthreads();
            }
            // out1 epilogue
#pragma unroll
            for (int m = 0; m < 2; m++) {
                const int r0 = mt * 32 + m * 16 + g;
#pragma unroll
                for (int j = 0; j < 2; j++) {
                    const int c = (nt * 2 + j) * 8 + t2 * 2;
#pragma unroll
                    for (int h2 = 0; h2 < 2; h2++) {
                        const int r = r0 + h2 * 8, node = nbase + r;
                        if (node < Nn) {
                            const float a = sAttr[r] * I21;
                            out[(size_t)node * 480 + 128 + c * 3 + i] =
                                acc2[m][j][h2 * 2] * a;
                            out[(size_t)node * 480 + 128 + (c + 1) * 3 + i] =
                                acc2[m][j][h2 * 2 + 1] * a;
                        }
                    }
                }
            }
        }
    }

    // ===== P3: mid2_i -> out2_i fused (i=0..4) =====
    // X2 at 512/5632; W1_2 at 10752/18432; W2_2 at 26112/32768; mid 46592/59904
    {
        uint16_t* mH = (uint16_t*)(smem + 46592);
        uint16_t* mL = (uint16_t*)(smem + 59904);
        for (int i = 0; i < 5; i++) {
            CP_WAIT0();
            __syncthreads();
            float acc[2][3][4];
            zacc<3>(acc);
            mma_tile<2, 3>(sb + 512, sb + 5632, sb + 10752, sb + 18432, 40,
                           mt * 32, nt * 3, lane, acc);
            __syncthreads();
            // mid epilogue -> smem, then convert next X2 slice
#pragma unroll
            for (int m = 0; m < 2; m++) {
                const int r0 = mt * 32 + m * 16 + g;
#pragma unroll
                for (int j = 0; j < 3; j++) {
                    const int c = (nt * 3 + j) * 8 + t2 * 2;
#pragma unroll
                    for (int h2 = 0; h2 < 2; h2++) {
                        const int r = r0 + h2 * 8;
                        const float a = sAttr[r] * I12;
                        const float2 gg = *reinterpret_cast<const float2*>(
                            gate + r * 288 + 192 + c);
                        st_pair(mH, mL, r * 104 + c, acc[m][j][h2 * 2] * a * gg.x,
                                acc[m][j][h2 * 2 + 1] * a * gg.y);
                    }
                }
            }
            if (i < 4)
                conv_str<4, 5>(sb + 512, sb + 5632, X, nbase, Nn, 320 + i + 1, 80);
            __syncthreads();
            float acc2[2][1][4];
            zacc<1>(acc2);
            mma_tile<6, 1>(sb + 46592, sb + 59904, sb + 26112, sb + 32768, 104,
                           mt * 32, nt, lane, acc2);
            __syncthreads();
#pragma unroll
            for (int m = 0; m < 2; m++) {
                const int r0 = mt * 32 + m * 16 + g;
                const int c = nt * 8 + t2 * 2;
#pragma unroll
                for (int h2 = 0; h2 < 2; h2++) {
                    const int r = r0 + h2 * 8, node = nbase + r;
                    if (node < Nn) {
                        const float a = sAttr[r] * I22;
                        out[(size_t)node * 480 + 320 + c * 5 + i] =
                            acc2[m][0][h2 * 2] * a;
                        out[(size_t)node * 480 + 320 + (c + 1) * 5 + i] =
                            acc2[m][0][h2 * 2 + 1] * a;
                    }
                }
            }
        }
    }
}

extern "C" void kernel_launch(void* const* d_in, const int* in_sizes, int n_in,
                              void* d_out, int out_size) {
    const float* X    = (const float*)d_in[0];
    const float* attr = (const float*)d_in[1];
    const float* W1_0 = (const float*)d_in[2];
    const float* W1_1 = (const float*)d_in[3];
    const float* W1_2 = (const float*)d_in[4];
    const float* b1   = (const float*)d_in[5];
    const float* W2_0 = (const float*)d_in[6];
    const float* W2_1 = (const float*)d_in[7];
    const float* W2_2 = (const float*)d_in[8];
    const float* b2   = (const float*)d_in[9];
    float* out = (float*)d_out;

    const int N = in_sizes[0] / 480;
    int nct = (N + 63) / 64;
    if (nct > MAXCTA) nct = MAXCTA;

    prep<<<160, 256>>>(W1_0, W1_1, W1_2, W2_0, W2_1, W2_2);
    cudaFuncSetAttribute(ffn_main, cudaFuncAttributeMaxDynamicSharedMemorySize, SM_TOT);
    ffn_main<<<nct, THREADS, SM_TOT>>>(X, attr, b1, b2, out, N);
}